// round 13
// baseline (speedup 1.0000x reference)
#include <cuda_runtime.h>
#include <cstdint>

#define BB 2
#define TT 4096
#define HH 8
#define HD 64
#define DM 512
#define BT (BB*TT)

// Scratch (__device__ globals; no allocs allowed)
__device__ float g_q[BB*HH*TT*HD];
__device__ float g_k[BB*HH*TT*HD];
__device__ float g_v[BB*HH*TT*HD];
__device__ float g_vt[BB*HH*HD*TT];   // transposed, tf32-rounded V
__device__ float g_y[(size_t)BT*DM];

// ===========================================================================
// helpers
// ===========================================================================
__device__ __forceinline__ uint32_t smem_u32(const void* p) {
    uint32_t a;
    asm("{ .reg .u64 t; cvta.to.shared.u64 t, %1; cvt.u32.u64 %0, t; }"
        : "=r"(a) : "l"(p));
    return a;
}
__device__ __forceinline__ uint32_t cvt_tf32(float x) {
    uint32_t u;
    asm("cvt.rna.tf32.f32 %0, %1;" : "=r"(u) : "f"(x));
    return u;
}
__device__ __forceinline__ uint32_t cvt_tf32u(uint32_t x) {
    uint32_t u;
    asm("cvt.rna.tf32.f32 %0, %1;" : "=r"(u) : "r"(x));
    return u;
}
__device__ __forceinline__ void ldsm4(uint32_t a[4], uint32_t addr) {
    asm volatile("ldmatrix.sync.aligned.m8n8.x4.shared.b16 {%0,%1,%2,%3}, [%4];"
        : "=r"(a[0]), "=r"(a[1]), "=r"(a[2]), "=r"(a[3]) : "r"(addr));
}
__device__ __forceinline__ void mma8(float c[4], const uint32_t a[4],
                                     uint32_t b0, uint32_t b1) {
    asm volatile(
        "mma.sync.aligned.m16n8k8.row.col.f32.tf32.tf32.f32 "
        "{%0,%1,%2,%3}, {%4,%5,%6,%7}, {%8,%9}, {%0,%1,%2,%3};"
        : "+f"(c[0]), "+f"(c[1]), "+f"(c[2]), "+f"(c[3])
        : "r"(a[0]), "r"(a[1]), "r"(a[2]), "r"(a[3]), "r"(b0), "r"(b1));
}
__device__ __forceinline__ void mma16(float c[4], const uint32_t a[4],
                                      uint32_t b0, uint32_t b1) {
    asm volatile(
        "mma.sync.aligned.m16n8k16.row.col.f32.bf16.bf16.f32 "
        "{%0,%1,%2,%3}, {%4,%5,%6,%7}, {%8,%9}, {%0,%1,%2,%3};"
        : "+f"(c[0]), "+f"(c[1]), "+f"(c[2]), "+f"(c[3])
        : "r"(a[0]), "r"(a[1]), "r"(a[2]), "r"(a[3]), "r"(b0), "r"(b1));
}
__device__ __forceinline__ void split_bf16(float v, uint16_t& h, uint16_t& l) {
    asm("cvt.rn.bf16.f32 %0, %1;" : "=h"(h) : "f"(v));
    float hf = __uint_as_float((uint32_t)h << 16);
    asm("cvt.rn.bf16.f32 %0, %1;" : "=h"(l) : "f"(v - hf));
}

#define CP16(dst, src) \
    asm volatile("cp.async.cg.shared.global [%0], [%1], 16;" \
                 :: "r"(dst), "l"(src) : "memory")
#define CPCOMMIT() asm volatile("cp.async.commit_group;" ::: "memory")
#define CPWAIT1()  asm volatile("cp.async.wait_group 1;" ::: "memory")
#define CPWAIT0()  asm volatile("cp.async.wait_group 0;" ::: "memory")

// ===========================================================================
// QKV projection: bf16 split hi/lo, 3 mma products, register-staged
// 2-deep pipeline (ONE sync per k-chunk; convert overlaps other warps' mma).
// C = x @ W^T. CTA 128x128, 8 warps (2x4), warp tile 64x32, kchunk 32.
// grid = (4, 64, 3). smem: 2 stages x (Ah/Al/Bh/Bl [128][40] bf16) = 80KB.
// ===========================================================================
#define QKV_STAGE_W 10240            // uint32 words per stage (4 tiles x 2560)
#define QKV_SMEM (2 * QKV_STAGE_W * 4)

__global__ __launch_bounds__(256, 2) void qkv_mma_kernel(
    const float* __restrict__ x,
    const float* __restrict__ Wq, const float* __restrict__ Wk,
    const float* __restrict__ Wv) {
    extern __shared__ uint32_t smq[];
    uint32_t sb = smem_u32(smq);

    const float* W = (blockIdx.z == 0) ? Wq : (blockIdx.z == 1) ? Wk : Wv;
    float* outp    = (blockIdx.z == 0) ? g_q : (blockIdx.z == 1) ? g_k : g_v;

    int m0 = blockIdx.y * 128, n0 = blockIdx.x * 128;
    int tid = threadIdx.x, lane = tid & 31, wid = tid >> 5;
    int wm = wid >> 2, wn = wid & 3;

    float c[16][4] = {};

    int lrow = (lane & 7) + ((lane >> 3) & 1) * 8;
    int lk   = (lane >> 4) * 8;

    // this thread's 4 (row, kq) chunks per tile
    int rows_[4], kqs_[4];
#pragma unroll
    for (int i = 0; i < 4; i++) {
        int id = tid + i * 256;
        rows_[i] = id >> 3;
        kqs_[i]  = (id & 7) * 4;
    }

    // prefetch kc = 0
    float4 va[4], vb[4];
#pragma unroll
    for (int i = 0; i < 4; i++) {
        va[i] = *(const float4*)(x + (size_t)(m0 + rows_[i]) * DM + kqs_[i]);
        vb[i] = *(const float4*)(W + (size_t)(n0 + rows_[i]) * DM + kqs_[i]);
    }

    for (int kc = 0; kc < 16; kc++) {
        uint32_t soff = (uint32_t)(kc & 1) * QKV_STAGE_W;
        uint32_t* Ah32 = smq + soff;
        uint32_t* Al32 = smq + soff + 2560;
        uint32_t* Bh32 = smq + soff + 5120;
        uint32_t* Bl32 = smq + soff + 7680;

        // convert staged regs -> smem stage (kc & 1)
#pragma unroll
        for (int i = 0; i < 4; i++) {
            int idx = rows_[i] * 20 + (kqs_[i] >> 1);
            uint16_t hx, lx, hy, ly, hz, lz, hw, lw;
            split_bf16(va[i].x, hx, lx); split_bf16(va[i].y, hy, ly);
            split_bf16(va[i].z, hz, lz); split_bf16(va[i].w, hw, lw);
            Ah32[idx]     = (uint32_t)hx | ((uint32_t)hy << 16);
            Ah32[idx + 1] = (uint32_t)hz | ((uint32_t)hw << 16);
            Al32[idx]     = (uint32_t)lx | ((uint32_t)ly << 16);
            Al32[idx + 1] = (uint32_t)lz | ((uint32_t)lw << 16);
            split_bf16(vb[i].x, hx, lx); split_bf16(vb[i].y, hy, ly);
            split_bf16(vb[i].z, hz, lz); split_bf16(vb[i].w, hw, lw);
            Bh32[idx]     = (uint32_t)hx | ((uint32_t)hy << 16);
            Bh32[idx + 1] = (uint32_t)hz | ((uint32_t)hw << 16);
            Bl32[idx]     = (uint32_t)lx | ((uint32_t)ly << 16);
            Bl32[idx + 1] = (uint32_t)lz | ((uint32_t)lw << 16);
        }
        __syncthreads();

        // prefetch kc+1 (LDG latency hides under the mma phase below)
        if (kc + 1 < 16) {
            int k0n = (kc + 1) * 32;
#pragma unroll
            for (int i = 0; i < 4; i++) {
                va[i] = *(const float4*)(x + (size_t)(m0 + rows_[i]) * DM + k0n + kqs_[i]);
                vb[i] = *(const float4*)(W + (size_t)(n0 + rows_[i]) * DM + k0n + kqs_[i]);
            }
        }

        uint32_t sAh = sb + soff * 4;
        uint32_t sAl = sAh + 10240;
        uint32_t sBh = sAh + 20480;
        uint32_t sBl = sAh + 30720;

#pragma unroll
        for (int ks = 0; ks < 2; ks++) {
            uint32_t boff0 = (uint32_t)((wn * 32 + lrow) * 40 + lk + ks * 16) * 2;
            uint32_t boff1 = (uint32_t)((wn * 32 + 16 + lrow) * 40 + lk + ks * 16) * 2;
            uint32_t bh0[4], bl0[4], bh1[4], bl1[4];
            ldsm4(bh0, sBh + boff0);
            ldsm4(bl0, sBl + boff0);
            ldsm4(bh1, sBh + boff1);
            ldsm4(bl1, sBl + boff1);
#pragma unroll
            for (int ma = 0; ma < 4; ma++) {
                uint32_t aoff = (uint32_t)((wm * 64 + ma * 16 + lrow) * 40 + lk + ks * 16) * 2;
                uint32_t ah[4], al[4];
                ldsm4(ah, sAh + aoff);
                ldsm4(al, sAl + aoff);
                mma16(c[ma * 4 + 0], ah, bh0[0], bh0[2]);
                mma16(c[ma * 4 + 0], ah, bl0[0], bl0[2]);
                mma16(c[ma * 4 + 0], al, bh0[0], bh0[2]);
                mma16(c[ma * 4 + 1], ah, bh0[1], bh0[3]);
                mma16(c[ma * 4 + 1], ah, bl0[1], bl0[3]);
                mma16(c[ma * 4 + 1], al, bh0[1], bh0[3]);
                mma16(c[ma * 4 + 2], ah, bh1[0], bh1[2]);
                mma16(c[ma * 4 + 2], ah, bl1[0], bl1[2]);
                mma16(c[ma * 4 + 2], al, bh1[0], bh1[2]);
                mma16(c[ma * 4 + 3], ah, bh1[1], bh1[3]);
                mma16(c[ma * 4 + 3], ah, bl1[1], bl1[3]);
                mma16(c[ma * 4 + 3], al, bh1[1], bh1[3]);
            }
        }
    }

    // epilogue -> (B,H,T,hd)
#pragma unroll
    for (int ma = 0; ma < 4; ma++) {
#pragma unroll
        for (int na = 0; na < 4; na++) {
            int n = n0 + wn * 32 + na * 8 + 2 * (lane & 3);
            int h = n >> 6, d = n & 63;
#pragma unroll
            for (int half = 0; half < 2; half++) {
                int m = m0 + wm * 64 + ma * 16 + (lane >> 2) + half * 8;
                int b = m >> 12, t = m & (TT - 1);
                float2 v = make_float2(c[ma * 4 + na][half * 2],
                                       c[ma * 4 + na][half * 2 + 1]);
                *(float2*)&outp[(((size_t)(b * HH + h)) * TT + t) * HD + d] = v;
            }
        }
    }
}

// ===========================================================================
// Prep: RoPE + (scale*log2e) + tf32 for q, RoPE+tf32 for k (in place);
// V -> tf32 + transpose into g_vt[bh][d][t]. grid = (TT/64, BB*HH).
// ===========================================================================
#define QSCALE 0.1803368801111204f   /* 0.125 * log2(e) */

__global__ __launch_bounds__(256) void prep_kernel(
    const float* __restrict__ cosp, const float* __restrict__ sinp) {
    __shared__ float vs[64][65];
    int bh = blockIdx.y;
    int t0 = blockIdx.x * 64;
    int tid = threadIdx.x;
    float* Qg = g_q + (size_t)bh * TT * HD;
    float* Kg = g_k + (size_t)bh * TT * HD;
    const float* Vg = g_v + (size_t)bh * TT * HD;
    float* Vtg = g_vt + (size_t)bh * HD * TT;

#pragma unroll
    for (int i = 0; i < 8; i++) {
        int p = tid + i * 256;
        int t = t0 + (p >> 5), j = p & 31;
        float cs = cosp[t * 32 + j], sn = sinp[t * 32 + j];
        float q1 = Qg[t * HD + j], q2 = Qg[t * HD + j + 32];
        Qg[t * HD + j]      = __uint_as_float(cvt_tf32((q1 * cs + q2 * sn) * QSCALE));
        Qg[t * HD + j + 32] = __uint_as_float(cvt_tf32((-q1 * sn + q2 * cs) * QSCALE));
        float k1 = Kg[t * HD + j], k2 = Kg[t * HD + j + 32];
        Kg[t * HD + j]      = __uint_as_float(cvt_tf32(k1 * cs + k2 * sn));
        Kg[t * HD + j + 32] = __uint_as_float(cvt_tf32(-k1 * sn + k2 * cs));
    }
#pragma unroll
    for (int i = 0; i < 16; i++) {
        int p = tid + i * 256;
        int t = p >> 6, d = p & 63;
        vs[t][d] = __uint_as_float(cvt_tf32(Vg[(size_t)(t0 + t) * HD + d]));
    }
    __syncthreads();
#pragma unroll
    for (int i = 0; i < 16; i++) {
        int p = tid + i * 256;
        int d = p >> 6, t = p & 63;
        Vtg[(size_t)d * TT + t0 + t] = vs[t][d];
    }
}

// ===========================================================================
// Output projection: tf32 mma, cp.async double buffered fp32 tiles,
// rna-tf32 rounding applied to ldsm fragments. grid = (4, 64), 2 CTAs/SM.
// ===========================================================================
#define PTILE 18432                  // 128*36*4
#define PSTAGE (2 * PTILE)           // 36864
#define PROJ_SMEM (2 * PSTAGE)       // 73728

__global__ __launch_bounds__(256, 2) void proj_mma_kernel(
    const float* __restrict__ Wp, float* __restrict__ out) {
    extern __shared__ uint32_t smp[];
    uint32_t sb = smem_u32(smp);

    int m0 = blockIdx.y * 128, n0 = blockIdx.x * 128;
    int tid = threadIdx.x, lane = tid & 31, wid = tid >> 5;
    int wm = wid >> 2, wn = wid & 3;

    float c[16][4] = {};
    int arow = wm * 64 + (lane & 7) + ((lane >> 3) & 1) * 8;
    int acol = (lane >> 4) * 4;
    int brow = wn * 32 + (lane & 7) + (lane >> 4) * 8;
    int bcol = ((lane >> 3) & 1) * 4;

    // preload stage 0
#pragma unroll
    for (int i = 0; i < 4; i++) {
        int id = tid + i * 256;
        int row = id >> 3, ch = (id & 7) * 4;
        CP16(sb + (uint32_t)(row * 36 + ch) * 4, g_y + (size_t)(m0 + row) * DM + ch);
        CP16(sb + PTILE + (uint32_t)(row * 36 + ch) * 4, Wp + (size_t)(n0 + row) * DM + ch);
    }
    CPCOMMIT();

    for (int kc = 0; kc < 16; kc++) {
        if (kc + 1 < 16) {
            uint32_t st = sb + ((kc + 1) & 1) * PSTAGE;
            int k0 = (kc + 1) * 32;
#pragma unroll
            for (int i = 0; i < 4; i++) {
                int id = tid + i * 256;
                int row = id >> 3, ch = (id & 7) * 4;
                CP16(st + (uint32_t)(row * 36 + ch) * 4,
                     g_y + (size_t)(m0 + row) * DM + k0 + ch);
                CP16(st + PTILE + (uint32_t)(row * 36 + ch) * 4,
                     Wp + (size_t)(n0 + row) * DM + k0 + ch);
            }
            CPCOMMIT();
            CPWAIT1();
        } else {
            CPWAIT0();
        }
        __syncthreads();

        uint32_t sA = sb + (kc & 1) * PSTAGE;
        uint32_t sB = sA + PTILE;

#pragma unroll
        for (int ks = 0; ks < 4; ks++) {
            uint32_t a[4][4];
#pragma unroll
            for (int ma = 0; ma < 4; ma++) {
                ldsm4(a[ma], sA + (uint32_t)((arow + ma * 16) * 36 + acol + ks * 8) * 4);
#pragma unroll
                for (int j = 0; j < 4; j++) a[ma][j] = cvt_tf32u(a[ma][j]);
            }
#pragma unroll
            for (int p = 0; p < 2; p++) {
                uint32_t b[4];
                ldsm4(b, sB + (uint32_t)((brow + p * 16) * 36 + bcol + ks * 8) * 4);
#pragma unroll
                for (int j = 0; j < 4; j++) b[j] = cvt_tf32u(b[j]);
#pragma unroll
                for (int ma = 0; ma < 4; ma++) {
                    mma8(c[ma * 4 + 2 * p], a[ma], b[0], b[1]);
                    mma8(c[ma * 4 + 2 * p + 1], a[ma], b[2], b[3]);
                }
            }
        }
        __syncthreads();
    }

#pragma unroll
    for (int ma = 0; ma < 4; ma++) {
#pragma unroll
        for (int na = 0; na < 4; na++) {
            int n = n0 + wn * 32 + na * 8 + 2 * (lane & 3);
#pragma unroll
            for (int half = 0; half < 2; half++) {
                int m = m0 + wm * 64 + ma * 16 + (lane >> 2) + half * 8;
                float2 v = make_float2(c[ma * 4 + na][half * 2],
                                       c[ma * 4 + na][half * 2 + 1]);
                *(float2*)&out[(size_t)m * DM + n] = v;
            }
        }
    }
}

// ===========================================================================
// Flash attention (R9/R12 body), tf32 mma, q-tile 256, 512 threads. PAIRED
// q-tiles (qt = 15-bx then bx) -> uniform 17 k-tiles/CTA, grid (8,16).
// SMEM: Q[256][68] + 2x K[128][68] + 2x Vt[64][132] = 202KB
// ===========================================================================
#define MQ 256
#define KBUF   34816             // 128*68*4
#define VTBUF  33792             // 64*132*4
#define SK_OFF 69632             // after Q 256*68*4
#define SVT_OFF 139264
#define ATTN_SMEM 206848

__global__ __launch_bounds__(512) void attn_mma_kernel() {
    extern __shared__ float sma[];
    uint32_t sb = smem_u32(sma);
    uint32_t sQ = sb;

    int tid = threadIdx.x, lane = tid & 31, wid = tid >> 5;
    int bx = blockIdx.x;        // 0..7
    int bh = blockIdx.y;

    const float* Qg  = g_q  + (size_t)bh * TT * HD;
    const float* Kg  = g_k  + (size_t)bh * TT * HD;
    const float* Vtg = g_vt + (size_t)bh * HD * TT;

    int qrow = wid * 16 + (lane & 7) + ((lane >> 3) & 1) * 8;
    uint32_t qbase = sQ + (uint32_t)(qrow * 68 + (lane >> 4) * 4) * 4;
    uint32_t klane = (uint32_t)(((lane & 7) + (lane >> 4) * 8) * 68 + ((lane >> 3) & 1) * 4) * 4;
    uint32_t vlane = (uint32_t)(((lane & 7) + (lane >> 4) * 8) * 132 + ((lane >> 3) & 1) * 4) * 4;
    int myr0 = wid * 16 + (lane >> 2);

#pragma unroll 1
    for (int pass = 0; pass < 2; pass++) {
        int qt = pass ? bx : (15 - bx);   // big tile first
        int q0 = qt * MQ;

        // Q tile: 256x64 -> 4096 16B chunks, 8/thread
#pragma unroll
        for (int i = 0; i < 8; i++) {
            int id = tid + i * 512;
            int r = id >> 4, c4 = (id & 15) * 4;
            CP16(sQ + (uint32_t)(r * 68 + c4) * 4, Qg + (size_t)(q0 + r) * HD + c4);
        }
        // K/Vt tile 0 -> buf 0
#pragma unroll
        for (int i = 0; i < 4; i++) {
            int id = tid + i * 512;
            int r = id >> 4, c4 = (id & 15) * 4;
            CP16(sb + SK_OFF + (uint32_t)(r * 68 + c4) * 4, Kg + (size_t)r * HD + c4);
            int d = id >> 5, c8 = (id & 31) * 4;
            CP16(sb + SVT_OFF + (uint32_t)(d * 132 + c8) * 4, Vtg + (size_t)d * TT + c8);
        }
        CPCOMMIT();

        float o[8][4] = {};
        float lsum0 = 0.f, lsum1 = 0.f;
        int wrow_lo = q0 + wid * 16;
        int wrow_hi = wrow_lo + 15;
        int nk = (q0 + MQ) >> 7;

        for (int kt = 0; kt < nk; kt++) {
            if (kt + 1 < nk) {
                int buf = (kt + 1) & 1;
                const float* Ks = Kg + (size_t)(kt + 1) * 128 * HD;
                const float* Vs = Vtg + (size_t)(kt + 1) * 128;
#pragma unroll
                for (int i = 0; i < 4; i++) {
                    int id = tid + i * 512;
                    int r = id >> 4, c4 = (id & 15) * 4;
                    CP16(sb + SK_OFF + buf * KBUF + (uint32_t)(r * 68 + c4) * 4,
                         Ks + (size_t)r * HD + c4);
                    int d = id >> 5, c8 = (id & 31) * 4;
                    CP16(sb + SVT_OFF + buf * VTBUF + (uint32_t)(d * 132 + c8) * 4,
                         Vs + (size_t)d * TT + c8);
                }
                CPCOMMIT();
                CPWAIT1();
            } else {
                CPWAIT0();
            }
            __syncthreads();

            uint32_t kb = sb + SK_OFF + (kt & 1) * KBUF + klane;
            uint32_t vb = sb + SVT_OFF + (kt & 1) * VTBUF + vlane;

#pragma unroll
            for (int h = 0; h < 2; h++) {
                int col0 = kt * 128 + h * 64;
                if (col0 > wrow_hi) continue;

                // S = Q K^T : 16x64, K=64 (8 ksteps)
                float c[32];
#pragma unroll
                for (int i = 0; i < 32; i++) c[i] = 0.f;
#pragma unroll
                for (int ks = 0; ks < 8; ks++) {
                    uint32_t a[4];
                    ldsm4(a, qbase + ks * 32);
#pragma unroll
                    for (int p = 0; p < 4; p++) {
                        uint32_t b[4];
                        ldsm4(b, kb + (uint32_t)((h * 64 + p * 16) * 68) * 4 + ks * 32);
                        mma8(&c[(2 * p) * 4], a, b[0], b[1]);
                        mma8(&c[(2 * p + 1) * 4], a, b[2], b[3]);
                    }
                }

                // softmax via exp2 + causal mask; P rounded rna to tf32
                bool needmask = (col0 + 63 > wrow_lo);
#pragma unroll
                for (int na = 0; na < 8; na++) {
#pragma unroll
                    for (int q = 0; q < 4; q++) {
                        float p = exp2f(c[na * 4 + q]);
                        if (needmask) {
                            int colg = col0 + na * 8 + 2 * (lane & 3) + (q & 1);
                            int rowg = q0 + myr0 + (q >> 1) * 8;
                            if (colg > rowg) p = 0.f;
                        }
                        if (q < 2) lsum0 += p; else lsum1 += p;
                        c[na * 4 + q] = __uint_as_float(cvt_tf32(p));
                    }
                }

                // O += P V
                int src  = (lane & 28) | ((lane & 3) >> 1);
                int src2 = src + 2;
                bool odd = lane & 1;
#pragma unroll
                for (int kk = 0; kk < 8; kk++) {
                    float f0 = __shfl_sync(0xffffffffu, c[kk * 4 + 0], src);
                    float f1 = __shfl_sync(0xffffffffu, c[kk * 4 + 1], src);
                    float f2 = __shfl_sync(0xffffffffu, c[kk * 4 + 2], src);
                    float f3 = __shfl_sync(0xffffffffu, c[kk * 4 + 3], src);
                    float g0 = __shfl_sync(0xffffffffu, c[kk * 4 + 0], src2);
                    float g1 = __shfl_sync(0xffffffffu, c[kk * 4 + 1], src2);
                    float g2 = __shfl_sync(0xffffffffu, c[kk * 4 + 2], src2);
                    float g3 = __shfl_sync(0xffffffffu, c[kk * 4 + 3], src2);
                    uint32_t a[4];
                    a[0] = __float_as_uint(odd ? f1 : f0);
                    a[1] = __float_as_uint(odd ? f3 : f2);
                    a[2] = __float_as_uint(odd ? g1 : g0);
                    a[3] = __float_as_uint(odd ? g3 : g2);
#pragma unroll
                    for (int pb = 0; pb < 4; pb++) {
                        uint32_t b[4];
                        ldsm4(b, vb + (uint32_t)(pb * 16 * 132) * 4 + (h * 8 + kk) * 32);
                        mma8(o[pb * 2], a, b[0], b[1]);
                        mma8(o[pb * 2 + 1], a, b[2], b[3]);
                    }
                }
            }
            __syncthreads();
        }

        lsum0 += __shfl_xor_sync(0xffffffffu, lsum0, 1);
        lsum0 += __shfl_xor_sync(0xffffffffu, lsum0, 2);
        lsum1 += __shfl_xor_sync(0xffffffffu, lsum1, 1);
        lsum1 += __shfl_xor_sync(0xffffffffu, lsum1, 2);
        float inv0 = 1.f / lsum0, inv1 = 1.f / lsum1;

        int b = bh >> 3, h = bh & 7;
        int t0 = q0 + myr0, t1 = t0 + 8;
        float* dst0 = g_y + ((size_t)(b * TT + t0)) * DM + h * 64;
        float* dst1 = g_y + ((size_t)(b * TT + t1)) * DM + h * 64;
#pragma unroll
        for (int nd = 0; nd < 8; nd++) {
            int col = nd * 8 + 2 * (lane & 3);
            *(float2*)(dst0 + col) = make_float2(o[nd][0] * inv0, o[nd][1] * inv0);
            *(float2*)(dst1 + col) = make_float2(o[nd][2] * inv1, o[nd][3] * inv1);
        }
        __syncthreads();   // all warps done with smem before next pass reloads
    }
}

// ===========================================================================
extern "C" void kernel_launch(void* const* d_in, const int* in_sizes, int n_in,
                              void* d_out, int out_size) {
    const float* x    = (const float*)d_in[0];
    const float* cosp = (const float*)d_in[1];
    const float* sinp = (const float*)d_in[2];
    const float* Wq   = (const float*)d_in[3];
    const float* Wk   = (const float*)d_in[4];
    const float* Wv   = (const float*)d_in[5];
    const float* Wp   = (const float*)d_in[6];
    float* out = (float*)d_out;

    cudaFuncSetAttribute(qkv_mma_kernel,
                         cudaFuncAttributeMaxDynamicSharedMemorySize, QKV_SMEM);
    cudaFuncSetAttribute(attn_mma_kernel,
                         cudaFuncAttributeMaxDynamicSharedMemorySize, ATTN_SMEM);
    cudaFuncSetAttribute(proj_mma_kernel,
                         cudaFuncAttributeMaxDynamicSharedMemorySize, PROJ_SMEM);

    dim3 gq(DM / 128, BT / 128, 3);
    qkv_mma_kernel<<<gq, 256, QKV_SMEM>>>(x, Wq, Wk, Wv);

    dim3 gp0(TT / 64, BB * HH);
    prep_kernel<<<gp0, 256>>>(cosp, sinp);

    dim3 ga(TT / (2 * MQ), BB * HH);
    attn_mma_kernel<<<ga, 512, ATTN_SMEM>>>();

    dim3 gp(DM / 128, BT / 128);
    proj_mma_kernel<<<gp, 256, PROJ_SMEM>>>(Wp, out);
}

// round 14
// speedup vs baseline: 1.0364x; 1.0364x over previous
#include <cuda_runtime.h>
#include <cstdint>

#define BB 2
#define TT 4096
#define HH 8
#define HD 64
#define DM 512
#define BT (BB*TT)

// Scratch (__device__ globals; no allocs allowed)
__device__ float g_q[BB*HH*TT*HD];
__device__ float g_k[BB*HH*TT*HD];
__device__ float g_vt[BB*HH*HD*TT];   // transposed, tf32-rounded V
__device__ float g_y[(size_t)BT*DM];

// ===========================================================================
// helpers
// ===========================================================================
__device__ __forceinline__ uint32_t smem_u32(const void* p) {
    uint32_t a;
    asm("{ .reg .u64 t; cvta.to.shared.u64 t, %1; cvt.u32.u64 %0, t; }"
        : "=r"(a) : "l"(p));
    return a;
}
__device__ __forceinline__ uint32_t cvt_tf32(float x) {
    uint32_t u;
    asm("cvt.rna.tf32.f32 %0, %1;" : "=r"(u) : "f"(x));
    return u;
}
__device__ __forceinline__ uint32_t cvt_tf32u(uint32_t x) {
    uint32_t u;
    asm("cvt.rna.tf32.f32 %0, %1;" : "=r"(u) : "r"(x));
    return u;
}
__device__ __forceinline__ void ldsm4(uint32_t a[4], uint32_t addr) {
    asm volatile("ldmatrix.sync.aligned.m8n8.x4.shared.b16 {%0,%1,%2,%3}, [%4];"
        : "=r"(a[0]), "=r"(a[1]), "=r"(a[2]), "=r"(a[3]) : "r"(addr));
}
__device__ __forceinline__ void mma8(float c[4], const uint32_t a[4],
                                     uint32_t b0, uint32_t b1) {
    asm volatile(
        "mma.sync.aligned.m16n8k8.row.col.f32.tf32.tf32.f32 "
        "{%0,%1,%2,%3}, {%4,%5,%6,%7}, {%8,%9}, {%0,%1,%2,%3};"
        : "+f"(c[0]), "+f"(c[1]), "+f"(c[2]), "+f"(c[3])
        : "r"(a[0]), "r"(a[1]), "r"(a[2]), "r"(a[3]), "r"(b0), "r"(b1));
}
__device__ __forceinline__ void mma16(float c[4], const uint32_t a[4],
                                      uint32_t b0, uint32_t b1) {
    asm volatile(
        "mma.sync.aligned.m16n8k16.row.col.f32.bf16.bf16.f32 "
        "{%0,%1,%2,%3}, {%4,%5,%6,%7}, {%8,%9}, {%0,%1,%2,%3};"
        : "+f"(c[0]), "+f"(c[1]), "+f"(c[2]), "+f"(c[3])
        : "r"(a[0]), "r"(a[1]), "r"(a[2]), "r"(a[3]), "r"(b0), "r"(b1));
}
__device__ __forceinline__ void split_bf16(float v, uint16_t& h, uint16_t& l) {
    asm("cvt.rn.bf16.f32 %0, %1;" : "=h"(h) : "f"(v));
    float hf = __uint_as_float((uint32_t)h << 16);
    asm("cvt.rn.bf16.f32 %0, %1;" : "=h"(l) : "f"(v - hf));
}

#define CP16(dst, src) \
    asm volatile("cp.async.cg.shared.global [%0], [%1], 16;" \
                 :: "r"(dst), "l"(src) : "memory")
#define CPCOMMIT() asm volatile("cp.async.commit_group;" ::: "memory")
#define CPWAIT1()  asm volatile("cp.async.wait_group 1;" ::: "memory")
#define CPWAIT0()  asm volatile("cp.async.wait_group 0;" ::: "memory")

// ===========================================================================
// QKV projection (R12 body): bf16 split hi/lo inline, 3 mma products.
// z==2 (V) epilogue: transpose via smem, write g_vt directly (tf32-rounded).
// CTA 128x128, 8 warps (2x4), warp tile 64x32, kchunk 32. grid (4,64,3).
// smem: Ah/Al/Bh/Bl bf16 tiles [128][40] = 40KB (epilogue reuses as 66KB f32)
// ===========================================================================
#define QKV_SMEM 69632   /* max(4*128*40*2, 128*132*4) + pad */

__global__ __launch_bounds__(256, 2) void qkv_mma_kernel(
    const float* __restrict__ x,
    const float* __restrict__ Wq, const float* __restrict__ Wk,
    const float* __restrict__ Wv) {
    extern __shared__ uint32_t smq[];
    uint32_t* Ah32 = smq;
    uint32_t* Al32 = smq + 2560;
    uint32_t* Bh32 = smq + 5120;
    uint32_t* Bl32 = smq + 7680;
    uint32_t sb = smem_u32(smq);
    uint32_t sAh = sb, sAl = sb + 10240, sBh = sb + 20480, sBl = sb + 30720;

    const float* W = (blockIdx.z == 0) ? Wq : (blockIdx.z == 1) ? Wk : Wv;

    int m0 = blockIdx.y * 128, n0 = blockIdx.x * 128;
    int tid = threadIdx.x, lane = tid & 31, wid = tid >> 5;
    int wm = wid >> 2, wn = wid & 3;

    float c[16][4] = {};

    int lrow = (lane & 7) + ((lane >> 3) & 1) * 8;
    int lk   = (lane >> 4) * 8;

    for (int kc = 0; kc < 16; kc++) {
        int k0 = kc * 32;
        __syncthreads();
#pragma unroll
        for (int i = 0; i < 4; i++) {
            int id = tid + i * 256;
            int row = id >> 3, kq = (id & 7) * 4;
            int idx = row * 20 + (kq >> 1);
            float4 v = *(const float4*)(x + (size_t)(m0 + row) * DM + k0 + kq);
            uint16_t hx, lx, hy, ly, hz, lz, hw, lw;
            split_bf16(v.x, hx, lx); split_bf16(v.y, hy, ly);
            split_bf16(v.z, hz, lz); split_bf16(v.w, hw, lw);
            Ah32[idx]     = (uint32_t)hx | ((uint32_t)hy << 16);
            Ah32[idx + 1] = (uint32_t)hz | ((uint32_t)hw << 16);
            Al32[idx]     = (uint32_t)lx | ((uint32_t)ly << 16);
            Al32[idx + 1] = (uint32_t)lz | ((uint32_t)lw << 16);
            float4 w = *(const float4*)(W + (size_t)(n0 + row) * DM + k0 + kq);
            split_bf16(w.x, hx, lx); split_bf16(w.y, hy, ly);
            split_bf16(w.z, hz, lz); split_bf16(w.w, hw, lw);
            Bh32[idx]     = (uint32_t)hx | ((uint32_t)hy << 16);
            Bh32[idx + 1] = (uint32_t)hz | ((uint32_t)hw << 16);
            Bl32[idx]     = (uint32_t)lx | ((uint32_t)ly << 16);
            Bl32[idx + 1] = (uint32_t)lz | ((uint32_t)lw << 16);
        }
        __syncthreads();

#pragma unroll
        for (int ks = 0; ks < 2; ks++) {
            uint32_t boff0 = (uint32_t)((wn * 32 + lrow) * 40 + lk + ks * 16) * 2;
            uint32_t boff1 = (uint32_t)((wn * 32 + 16 + lrow) * 40 + lk + ks * 16) * 2;
            uint32_t bh0[4], bl0[4], bh1[4], bl1[4];
            ldsm4(bh0, sBh + boff0);
            ldsm4(bl0, sBl + boff0);
            ldsm4(bh1, sBh + boff1);
            ldsm4(bl1, sBl + boff1);
#pragma unroll
            for (int ma = 0; ma < 4; ma++) {
                uint32_t aoff = (uint32_t)((wm * 64 + ma * 16 + lrow) * 40 + lk + ks * 16) * 2;
                uint32_t ah[4], al[4];
                ldsm4(ah, sAh + aoff);
                ldsm4(al, sAl + aoff);
                mma16(c[ma * 4 + 0], ah, bh0[0], bh0[2]);
                mma16(c[ma * 4 + 0], ah, bl0[0], bl0[2]);
                mma16(c[ma * 4 + 0], al, bh0[0], bh0[2]);
                mma16(c[ma * 4 + 1], ah, bh0[1], bh0[3]);
                mma16(c[ma * 4 + 1], ah, bl0[1], bl0[3]);
                mma16(c[ma * 4 + 1], al, bh0[1], bh0[3]);
                mma16(c[ma * 4 + 2], ah, bh1[0], bh1[2]);
                mma16(c[ma * 4 + 2], ah, bl1[0], bl1[2]);
                mma16(c[ma * 4 + 2], al, bh1[0], bh1[2]);
                mma16(c[ma * 4 + 3], ah, bh1[1], bh1[3]);
                mma16(c[ma * 4 + 3], ah, bl1[1], bl1[3]);
                mma16(c[ma * 4 + 3], al, bh1[1], bh1[3]);
            }
        }
    }

    if (blockIdx.z == 2) {
        // V epilogue: transpose tile via smem, write g_vt coalesced
        float* smf = (float*)smq;
        __syncthreads();   // main-loop smem reads complete
#pragma unroll
        for (int ma = 0; ma < 4; ma++) {
#pragma unroll
            for (int na = 0; na < 4; na++) {
                int nl = wn * 32 + na * 8 + 2 * (lane & 3);
#pragma unroll
                for (int half = 0; half < 2; half++) {
                    int ml = wm * 64 + ma * 16 + (lane >> 2) + half * 8;
                    smf[(nl + 0) * 132 + ml] =
                        __uint_as_float(cvt_tf32(c[ma * 4 + na][half * 2]));
                    smf[(nl + 1) * 132 + ml] =
                        __uint_as_float(cvt_tf32(c[ma * 4 + na][half * 2 + 1]));
                }
            }
        }
        __syncthreads();
        int b = m0 >> 12;
        int t0 = m0 & (TT - 1);
#pragma unroll
        for (int i = 0; i < 16; i++) {
            int idx = tid + i * 256;           // 4096 float4 chunks
            int nl = idx >> 5, c4 = (idx & 31) * 4;
            float4 v = *(float4*)&smf[nl * 132 + c4];
            int n = n0 + nl;
            int h = n >> 6, d = n & 63;
            *(float4*)&g_vt[((size_t)(b * HH + h) * HD + d) * TT + t0 + c4] = v;
        }
    } else {
        float* outp = (blockIdx.z == 0) ? g_q : g_k;
        // epilogue -> (B,H,T,hd)
#pragma unroll
        for (int ma = 0; ma < 4; ma++) {
#pragma unroll
            for (int na = 0; na < 4; na++) {
                int n = n0 + wn * 32 + na * 8 + 2 * (lane & 3);
                int h = n >> 6, d = n & 63;
#pragma unroll
                for (int half = 0; half < 2; half++) {
                    int m = m0 + wm * 64 + ma * 16 + (lane >> 2) + half * 8;
                    int b = m >> 12, t = m & (TT - 1);
                    float2 v = make_float2(c[ma * 4 + na][half * 2],
                                           c[ma * 4 + na][half * 2 + 1]);
                    *(float2*)&outp[(((size_t)(b * HH + h)) * TT + t) * HD + d] = v;
                }
            }
        }
    }
}

// ===========================================================================
// Prep: RoPE + (scale*log2e) + tf32 for q, RoPE+tf32 for k (in place).
// V handled in qkv epilogue now. grid = (TT/64, BB*HH).
// ===========================================================================
#define QSCALE 0.1803368801111204f   /* 0.125 * log2(e) */

__global__ __launch_bounds__(256) void prep_kernel(
    const float* __restrict__ cosp, const float* __restrict__ sinp) {
    int bh = blockIdx.y;
    int t0 = blockIdx.x * 64;
    int tid = threadIdx.x;
    float* Qg = g_q + (size_t)bh * TT * HD;
    float* Kg = g_k + (size_t)bh * TT * HD;

#pragma unroll
    for (int i = 0; i < 8; i++) {
        int p = tid + i * 256;
        int t = t0 + (p >> 5), j = p & 31;
        float cs = cosp[t * 32 + j], sn = sinp[t * 32 + j];
        float q1 = Qg[t * HD + j], q2 = Qg[t * HD + j + 32];
        Qg[t * HD + j]      = __uint_as_float(cvt_tf32((q1 * cs + q2 * sn) * QSCALE));
        Qg[t * HD + j + 32] = __uint_as_float(cvt_tf32((-q1 * sn + q2 * cs) * QSCALE));
        float k1 = Kg[t * HD + j], k2 = Kg[t * HD + j + 32];
        Kg[t * HD + j]      = __uint_as_float(cvt_tf32(k1 * cs + k2 * sn));
        Kg[t * HD + j + 32] = __uint_as_float(cvt_tf32(-k1 * sn + k2 * cs));
    }
}

// ===========================================================================
// Output projection: tf32 mma, cp.async double buffered fp32 tiles,
// rna-tf32 rounding applied to ldsm fragments. grid = (4, 64), 2 CTAs/SM.
// ===========================================================================
#define PTILE 18432                  // 128*36*4
#define PSTAGE (2 * PTILE)           // 36864
#define PROJ_SMEM (2 * PSTAGE)       // 73728

__global__ __launch_bounds__(256, 2) void proj_mma_kernel(
    const float* __restrict__ Wp, float* __restrict__ out) {
    extern __shared__ uint32_t smp[];
    uint32_t sb = smem_u32(smp);

    int m0 = blockIdx.y * 128, n0 = blockIdx.x * 128;
    int tid = threadIdx.x, lane = tid & 31, wid = tid >> 5;
    int wm = wid >> 2, wn = wid & 3;

    float c[16][4] = {};
    int arow = wm * 64 + (lane & 7) + ((lane >> 3) & 1) * 8;
    int acol = (lane >> 4) * 4;
    int brow = wn * 32 + (lane & 7) + (lane >> 4) * 8;
    int bcol = ((lane >> 3) & 1) * 4;

    // preload stage 0
#pragma unroll
    for (int i = 0; i < 4; i++) {
        int id = tid + i * 256;
        int row = id >> 3, ch = (id & 7) * 4;
        CP16(sb + (uint32_t)(row * 36 + ch) * 4, g_y + (size_t)(m0 + row) * DM + ch);
        CP16(sb + PTILE + (uint32_t)(row * 36 + ch) * 4, Wp + (size_t)(n0 + row) * DM + ch);
    }
    CPCOMMIT();

    for (int kc = 0; kc < 16; kc++) {
        if (kc + 1 < 16) {
            uint32_t st = sb + ((kc + 1) & 1) * PSTAGE;
            int k0 = (kc + 1) * 32;
#pragma unroll
            for (int i = 0; i < 4; i++) {
                int id = tid + i * 256;
                int row = id >> 3, ch = (id & 7) * 4;
                CP16(st + (uint32_t)(row * 36 + ch) * 4,
                     g_y + (size_t)(m0 + row) * DM + k0 + ch);
                CP16(st + PTILE + (uint32_t)(row * 36 + ch) * 4,
                     Wp + (size_t)(n0 + row) * DM + k0 + ch);
            }
            CPCOMMIT();
            CPWAIT1();
        } else {
            CPWAIT0();
        }
        __syncthreads();

        uint32_t sA = sb + (kc & 1) * PSTAGE;
        uint32_t sB = sA + PTILE;

#pragma unroll
        for (int ks = 0; ks < 4; ks++) {
            uint32_t a[4][4];
#pragma unroll
            for (int ma = 0; ma < 4; ma++) {
                ldsm4(a[ma], sA + (uint32_t)((arow + ma * 16) * 36 + acol + ks * 8) * 4);
#pragma unroll
                for (int j = 0; j < 4; j++) a[ma][j] = cvt_tf32u(a[ma][j]);
            }
#pragma unroll
            for (int p = 0; p < 2; p++) {
                uint32_t b[4];
                ldsm4(b, sB + (uint32_t)((brow + p * 16) * 36 + bcol + ks * 8) * 4);
#pragma unroll
                for (int j = 0; j < 4; j++) b[j] = cvt_tf32u(b[j]);
#pragma unroll
                for (int ma = 0; ma < 4; ma++) {
                    mma8(c[ma * 4 + 2 * p], a[ma], b[0], b[1]);
                    mma8(c[ma * 4 + 2 * p + 1], a[ma], b[2], b[3]);
                }
            }
        }
        __syncthreads();
    }

#pragma unroll
    for (int ma = 0; ma < 4; ma++) {
#pragma unroll
        for (int na = 0; na < 4; na++) {
            int n = n0 + wn * 32 + na * 8 + 2 * (lane & 3);
#pragma unroll
            for (int half = 0; half < 2; half++) {
                int m = m0 + wm * 64 + ma * 16 + (lane >> 2) + half * 8;
                float2 v = make_float2(c[ma * 4 + na][half * 2],
                                       c[ma * 4 + na][half * 2 + 1]);
                *(float2*)&out[(size_t)m * DM + n] = v;
            }
        }
    }
}

// ===========================================================================
// Flash attention (R12 body), tf32 mma, q-tile 256, 512 threads. PAIRED
// q-tiles (qt = 15-bx then bx) -> uniform 17 k-tiles/CTA, grid (8,16).
// SMEM: Q[256][68] + 2x K[128][68] + 2x Vt[64][132] = 202KB
// ===========================================================================
#define MQ 256
#define KBUF   34816             // 128*68*4
#define VTBUF  33792             // 64*132*4
#define SK_OFF 69632             // after Q 256*68*4
#define SVT_OFF 139264
#define ATTN_SMEM 206848

__global__ __launch_bounds__(512) void attn_mma_kernel() {
    extern __shared__ float sma[];
    uint32_t sb = smem_u32(sma);
    uint32_t sQ = sb;

    int tid = threadIdx.x, lane = tid & 31, wid = tid >> 5;
    int bx = blockIdx.x;        // 0..7
    int bh = blockIdx.y;

    const float* Qg  = g_q  + (size_t)bh * TT * HD;
    const float* Kg  = g_k  + (size_t)bh * TT * HD;
    const float* Vtg = g_vt + (size_t)bh * HD * TT;

    int qrow = wid * 16 + (lane & 7) + ((lane >> 3) & 1) * 8;
    uint32_t qbase = sQ + (uint32_t)(qrow * 68 + (lane >> 4) * 4) * 4;
    uint32_t klane = (uint32_t)(((lane & 7) + (lane >> 4) * 8) * 68 + ((lane >> 3) & 1) * 4) * 4;
    uint32_t vlane = (uint32_t)(((lane & 7) + (lane >> 4) * 8) * 132 + ((lane >> 3) & 1) * 4) * 4;
    int myr0 = wid * 16 + (lane >> 2);

#pragma unroll 1
    for (int pass = 0; pass < 2; pass++) {
        int qt = pass ? bx : (15 - bx);   // big tile first
        int q0 = qt * MQ;

        // Q tile: 256x64 -> 4096 16B chunks, 8/thread
#pragma unroll
        for (int i = 0; i < 8; i++) {
            int id = tid + i * 512;
            int r = id >> 4, c4 = (id & 15) * 4;
            CP16(sQ + (uint32_t)(r * 68 + c4) * 4, Qg + (size_t)(q0 + r) * HD + c4);
        }
        // K/Vt tile 0 -> buf 0
#pragma unroll
        for (int i = 0; i < 4; i++) {
            int id = tid + i * 512;
            int r = id >> 4, c4 = (id & 15) * 4;
            CP16(sb + SK_OFF + (uint32_t)(r * 68 + c4) * 4, Kg + (size_t)r * HD + c4);
            int d = id >> 5, c8 = (id & 31) * 4;
            CP16(sb + SVT_OFF + (uint32_t)(d * 132 + c8) * 4, Vtg + (size_t)d * TT + c8);
        }
        CPCOMMIT();

        float o[8][4] = {};
        float lsum0 = 0.f, lsum1 = 0.f;
        int wrow_lo = q0 + wid * 16;
        int wrow_hi = wrow_lo + 15;
        int nk = (q0 + MQ) >> 7;

        for (int kt = 0; kt < nk; kt++) {
            if (kt + 1 < nk) {
                int buf = (kt + 1) & 1;
                const float* Ks = Kg + (size_t)(kt + 1) * 128 * HD;
                const float* Vs = Vtg + (size_t)(kt + 1) * 128;
#pragma unroll
                for (int i = 0; i < 4; i++) {
                    int id = tid + i * 512;
                    int r = id >> 4, c4 = (id & 15) * 4;
                    CP16(sb + SK_OFF + buf * KBUF + (uint32_t)(r * 68 + c4) * 4,
                         Ks + (size_t)r * HD + c4);
                    int d = id >> 5, c8 = (id & 31) * 4;
                    CP16(sb + SVT_OFF + buf * VTBUF + (uint32_t)(d * 132 + c8) * 4,
                         Vs + (size_t)d * TT + c8);
                }
                CPCOMMIT();
                CPWAIT1();
            } else {
                CPWAIT0();
            }
            __syncthreads();

            uint32_t kb = sb + SK_OFF + (kt & 1) * KBUF + klane;
            uint32_t vb = sb + SVT_OFF + (kt & 1) * VTBUF + vlane;

#pragma unroll
            for (int h = 0; h < 2; h++) {
                int col0 = kt * 128 + h * 64;
                if (col0 > wrow_hi) continue;

                // S = Q K^T : 16x64, K=64 (8 ksteps)
                float c[32];
#pragma unroll
                for (int i = 0; i < 32; i++) c[i] = 0.f;
#pragma unroll
                for (int ks = 0; ks < 8; ks++) {
                    uint32_t a[4];
                    ldsm4(a, qbase + ks * 32);
#pragma unroll
                    for (int p = 0; p < 4; p++) {
                        uint32_t b[4];
                        ldsm4(b, kb + (uint32_t)((h * 64 + p * 16) * 68) * 4 + ks * 32);
                        mma8(&c[(2 * p) * 4], a, b[0], b[1]);
                        mma8(&c[(2 * p + 1) * 4], a, b[2], b[3]);
                    }
                }

                // softmax via exp2 + causal mask; P rounded rna to tf32
                bool needmask = (col0 + 63 > wrow_lo);
#pragma unroll
                for (int na = 0; na < 8; na++) {
#pragma unroll
                    for (int q = 0; q < 4; q++) {
                        float p = exp2f(c[na * 4 + q]);
                        if (needmask) {
                            int colg = col0 + na * 8 + 2 * (lane & 3) + (q & 1);
                            int rowg = q0 + myr0 + (q >> 1) * 8;
                            if (colg > rowg) p = 0.f;
                        }
                        if (q < 2) lsum0 += p; else lsum1 += p;
                        c[na * 4 + q] = __uint_as_float(cvt_tf32(p));
                    }
                }

                // O += P V
                int src  = (lane & 28) | ((lane & 3) >> 1);
                int src2 = src + 2;
                bool odd = lane & 1;
#pragma unroll
                for (int kk = 0; kk < 8; kk++) {
                    float f0 = __shfl_sync(0xffffffffu, c[kk * 4 + 0], src);
                    float f1 = __shfl_sync(0xffffffffu, c[kk * 4 + 1], src);
                    float f2 = __shfl_sync(0xffffffffu, c[kk * 4 + 2], src);
                    float f3 = __shfl_sync(0xffffffffu, c[kk * 4 + 3], src);
                    float g0 = __shfl_sync(0xffffffffu, c[kk * 4 + 0], src2);
                    float g1 = __shfl_sync(0xffffffffu, c[kk * 4 + 1], src2);
                    float g2 = __shfl_sync(0xffffffffu, c[kk * 4 + 2], src2);
                    float g3 = __shfl_sync(0xffffffffu, c[kk * 4 + 3], src2);
                    uint32_t a[4];
                    a[0] = __float_as_uint(odd ? f1 : f0);
                    a[1] = __float_as_uint(odd ? f3 : f2);
                    a[2] = __float_as_uint(odd ? g1 : g0);
                    a[3] = __float_as_uint(odd ? g3 : g2);
#pragma unroll
                    for (int pb = 0; pb < 4; pb++) {
                        uint32_t b[4];
                        ldsm4(b, vb + (uint32_t)(pb * 16 * 132) * 4 + (h * 8 + kk) * 32);
                        mma8(o[pb * 2], a, b[0], b[1]);
                        mma8(o[pb * 2 + 1], a, b[2], b[3]);
                    }
                }
            }
            __syncthreads();
        }

        lsum0 += __shfl_xor_sync(0xffffffffu, lsum0, 1);
        lsum0 += __shfl_xor_sync(0xffffffffu, lsum0, 2);
        lsum1 += __shfl_xor_sync(0xffffffffu, lsum1, 1);
        lsum1 += __shfl_xor_sync(0xffffffffu, lsum1, 2);
        float inv0 = 1.f / lsum0, inv1 = 1.f / lsum1;

        int b = bh >> 3, h = bh & 7;
        int t0 = q0 + myr0, t1 = t0 + 8;
        float* dst0 = g_y + ((size_t)(b * TT + t0)) * DM + h * 64;
        float* dst1 = g_y + ((size_t)(b * TT + t1)) * DM + h * 64;
#pragma unroll
        for (int nd = 0; nd < 8; nd++) {
            int col = nd * 8 + 2 * (lane & 3);
            *(float2*)(dst0 + col) = make_float2(o[nd][0] * inv0, o[nd][1] * inv0);
            *(float2*)(dst1 + col) = make_float2(o[nd][2] * inv1, o[nd][3] * inv1);
        }
        __syncthreads();   // all warps done with smem before next pass reloads
    }
}

// ===========================================================================
extern "C" void kernel_launch(void* const* d_in, const int* in_sizes, int n_in,
                              void* d_out, int out_size) {
    const float* x    = (const float*)d_in[0];
    const float* cosp = (const float*)d_in[1];
    const float* sinp = (const float*)d_in[2];
    const float* Wq   = (const float*)d_in[3];
    const float* Wk   = (const float*)d_in[4];
    const float* Wv   = (const float*)d_in[5];
    const float* Wp   = (const float*)d_in[6];
    float* out = (float*)d_out;

    cudaFuncSetAttribute(qkv_mma_kernel,
                         cudaFuncAttributeMaxDynamicSharedMemorySize, QKV_SMEM);
    cudaFuncSetAttribute(attn_mma_kernel,
                         cudaFuncAttributeMaxDynamicSharedMemorySize, ATTN_SMEM);
    cudaFuncSetAttribute(proj_mma_kernel,
                         cudaFuncAttributeMaxDynamicSharedMemorySize, PROJ_SMEM);

    dim3 gq(DM / 128, BT / 128, 3);
    qkv_mma_kernel<<<gq, 256, QKV_SMEM>>>(x, Wq, Wk, Wv);

    dim3 gp0(TT / 64, BB * HH);
    prep_kernel<<<gp0, 256>>>(cosp, sinp);

    dim3 ga(TT / (2 * MQ), BB * HH);
    attn_mma_kernel<<<ga, 512, ATTN_SMEM>>>();

    dim3 gp(DM / 128, BT / 128);
    proj_mma_kernel<<<gp, 256, PROJ_SMEM>>>(Wp, out);
}

// round 15
// speedup vs baseline: 1.0583x; 1.0211x over previous
#include <cuda_runtime.h>
#include <cstdint>

#define BB 2
#define TT 4096
#define HH 8
#define HD 64
#define DM 512
#define BT (BB*TT)

// Scratch (__device__ globals; no allocs allowed)
__device__ float g_q[BB*HH*TT*HD];
__device__ float g_k[BB*HH*TT*HD];
__device__ float g_vt[BB*HH*HD*TT];   // transposed, tf32-rounded V
__device__ float g_y[(size_t)BT*DM];

// ===========================================================================
// helpers
// ===========================================================================
__device__ __forceinline__ uint32_t smem_u32(const void* p) {
    uint32_t a;
    asm("{ .reg .u64 t; cvta.to.shared.u64 t, %1; cvt.u32.u64 %0, t; }"
        : "=r"(a) : "l"(p));
    return a;
}
__device__ __forceinline__ uint32_t cvt_tf32(float x) {
    uint32_t u;
    asm("cvt.rna.tf32.f32 %0, %1;" : "=r"(u) : "f"(x));
    return u;
}
__device__ __forceinline__ uint32_t cvt_tf32u(uint32_t x) {
    uint32_t u;
    asm("cvt.rna.tf32.f32 %0, %1;" : "=r"(u) : "r"(x));
    return u;
}
__device__ __forceinline__ void ldsm4(uint32_t a[4], uint32_t addr) {
    asm volatile("ldmatrix.sync.aligned.m8n8.x4.shared.b16 {%0,%1,%2,%3}, [%4];"
        : "=r"(a[0]), "=r"(a[1]), "=r"(a[2]), "=r"(a[3]) : "r"(addr));
}
__device__ __forceinline__ void mma8(float c[4], const uint32_t a[4],
                                     uint32_t b0, uint32_t b1) {
    asm volatile(
        "mma.sync.aligned.m16n8k8.row.col.f32.tf32.tf32.f32 "
        "{%0,%1,%2,%3}, {%4,%5,%6,%7}, {%8,%9}, {%0,%1,%2,%3};"
        : "+f"(c[0]), "+f"(c[1]), "+f"(c[2]), "+f"(c[3])
        : "r"(a[0]), "r"(a[1]), "r"(a[2]), "r"(a[3]), "r"(b0), "r"(b1));
}
__device__ __forceinline__ void mma16(float c[4], const uint32_t a[4],
                                      uint32_t b0, uint32_t b1) {
    asm volatile(
        "mma.sync.aligned.m16n8k16.row.col.f32.bf16.bf16.f32 "
        "{%0,%1,%2,%3}, {%4,%5,%6,%7}, {%8,%9}, {%0,%1,%2,%3};"
        : "+f"(c[0]), "+f"(c[1]), "+f"(c[2]), "+f"(c[3])
        : "r"(a[0]), "r"(a[1]), "r"(a[2]), "r"(a[3]), "r"(b0), "r"(b1));
}
__device__ __forceinline__ void split_bf16(float v, uint16_t& h, uint16_t& l) {
    asm("cvt.rn.bf16.f32 %0, %1;" : "=h"(h) : "f"(v));
    float hf = __uint_as_float((uint32_t)h << 16);
    asm("cvt.rn.bf16.f32 %0, %1;" : "=h"(l) : "f"(v - hf));
}

#define CP16(dst, src) \
    asm volatile("cp.async.cg.shared.global [%0], [%1], 16;" \
                 :: "r"(dst), "l"(src) : "memory")
#define CPCOMMIT() asm volatile("cp.async.commit_group;" ::: "memory")
#define CPWAIT1()  asm volatile("cp.async.wait_group 1;" ::: "memory")
#define CPWAIT0()  asm volatile("cp.async.wait_group 0;" ::: "memory")

// ===========================================================================
// Q/K projection: bf16 split hi/lo inline, 3 mma products.
// C = x @ W^T. CTA 128x128, 8 warps (2x4), warp tile 64x32, kchunk 32.
// grid = (4, 64, 2). smem: Ah/Al/Bh/Bl bf16 tiles [128][40] = 40KB.
// ===========================================================================
#define QKV_SMEM (4 * 128 * 40 * 2)

__global__ __launch_bounds__(256, 2) void qkv_mma_kernel(
    const float* __restrict__ x,
    const float* __restrict__ Wq, const float* __restrict__ Wk) {
    extern __shared__ uint32_t smq[];
    uint32_t* Ah32 = smq;
    uint32_t* Al32 = smq + 2560;
    uint32_t* Bh32 = smq + 5120;
    uint32_t* Bl32 = smq + 7680;
    uint32_t sb = smem_u32(smq);
    uint32_t sAh = sb, sAl = sb + 10240, sBh = sb + 20480, sBl = sb + 30720;

    const float* W = (blockIdx.z == 0) ? Wq : Wk;
    float* outp    = (blockIdx.z == 0) ? g_q : g_k;

    int m0 = blockIdx.y * 128, n0 = blockIdx.x * 128;
    int tid = threadIdx.x, lane = tid & 31, wid = tid >> 5;
    int wm = wid >> 2, wn = wid & 3;

    float c[16][4] = {};

    int lrow = (lane & 7) + ((lane >> 3) & 1) * 8;
    int lk   = (lane >> 4) * 8;

    for (int kc = 0; kc < 16; kc++) {
        int k0 = kc * 32;
        __syncthreads();
#pragma unroll
        for (int i = 0; i < 4; i++) {
            int id = tid + i * 256;
            int row = id >> 3, kq = (id & 7) * 4;
            int idx = row * 20 + (kq >> 1);
            float4 v = *(const float4*)(x + (size_t)(m0 + row) * DM + k0 + kq);
            uint16_t hx, lx, hy, ly, hz, lz, hw, lw;
            split_bf16(v.x, hx, lx); split_bf16(v.y, hy, ly);
            split_bf16(v.z, hz, lz); split_bf16(v.w, hw, lw);
            Ah32[idx]     = (uint32_t)hx | ((uint32_t)hy << 16);
            Ah32[idx + 1] = (uint32_t)hz | ((uint32_t)hw << 16);
            Al32[idx]     = (uint32_t)lx | ((uint32_t)ly << 16);
            Al32[idx + 1] = (uint32_t)lz | ((uint32_t)lw << 16);
            float4 w = *(const float4*)(W + (size_t)(n0 + row) * DM + k0 + kq);
            split_bf16(w.x, hx, lx); split_bf16(w.y, hy, ly);
            split_bf16(w.z, hz, lz); split_bf16(w.w, hw, lw);
            Bh32[idx]     = (uint32_t)hx | ((uint32_t)hy << 16);
            Bh32[idx + 1] = (uint32_t)hz | ((uint32_t)hw << 16);
            Bl32[idx]     = (uint32_t)lx | ((uint32_t)ly << 16);
            Bl32[idx + 1] = (uint32_t)lz | ((uint32_t)lw << 16);
        }
        __syncthreads();

#pragma unroll
        for (int ks = 0; ks < 2; ks++) {
            uint32_t boff0 = (uint32_t)((wn * 32 + lrow) * 40 + lk + ks * 16) * 2;
            uint32_t boff1 = (uint32_t)((wn * 32 + 16 + lrow) * 40 + lk + ks * 16) * 2;
            uint32_t bh0[4], bl0[4], bh1[4], bl1[4];
            ldsm4(bh0, sBh + boff0);
            ldsm4(bl0, sBl + boff0);
            ldsm4(bh1, sBh + boff1);
            ldsm4(bl1, sBl + boff1);
#pragma unroll
            for (int ma = 0; ma < 4; ma++) {
                uint32_t aoff = (uint32_t)((wm * 64 + ma * 16 + lrow) * 40 + lk + ks * 16) * 2;
                uint32_t ah[4], al[4];
                ldsm4(ah, sAh + aoff);
                ldsm4(al, sAl + aoff);
                mma16(c[ma * 4 + 0], ah, bh0[0], bh0[2]);
                mma16(c[ma * 4 + 0], ah, bl0[0], bl0[2]);
                mma16(c[ma * 4 + 0], al, bh0[0], bh0[2]);
                mma16(c[ma * 4 + 1], ah, bh0[1], bh0[3]);
                mma16(c[ma * 4 + 1], ah, bl0[1], bl0[3]);
                mma16(c[ma * 4 + 1], al, bh0[1], bh0[3]);
                mma16(c[ma * 4 + 2], ah, bh1[0], bh1[2]);
                mma16(c[ma * 4 + 2], ah, bl1[0], bl1[2]);
                mma16(c[ma * 4 + 2], al, bh1[0], bh1[2]);
                mma16(c[ma * 4 + 3], ah, bh1[1], bh1[3]);
                mma16(c[ma * 4 + 3], ah, bl1[1], bl1[3]);
                mma16(c[ma * 4 + 3], al, bh1[1], bh1[3]);
            }
        }
    }

    // epilogue -> (B,H,T,hd)
#pragma unroll
    for (int ma = 0; ma < 4; ma++) {
#pragma unroll
        for (int na = 0; na < 4; na++) {
            int n = n0 + wn * 32 + na * 8 + 2 * (lane & 3);
            int h = n >> 6, d = n & 63;
#pragma unroll
            for (int half = 0; half < 2; half++) {
                int m = m0 + wm * 64 + ma * 16 + (lane >> 2) + half * 8;
                int b = m >> 12, t = m & (TT - 1);
                float2 v = make_float2(c[ma * 4 + na][half * 2],
                                       c[ma * 4 + na][half * 2 + 1]);
                *(float2*)&outp[(((size_t)(b * HH + h)) * TT + t) * HD + d] = v;
            }
        }
    }
}

// ===========================================================================
// Prep: RoPE + (scale*log2e) + tf32 for q, RoPE+tf32 for k (in place).
// grid = (TT/64, BB*HH).
// ===========================================================================
#define QSCALE 0.1803368801111204f   /* 0.125 * log2(e) */

__global__ __launch_bounds__(256) void prep_kernel(
    const float* __restrict__ cosp, const float* __restrict__ sinp) {
    int bh = blockIdx.y;
    int t0 = blockIdx.x * 64;
    int tid = threadIdx.x;
    float* Qg = g_q + (size_t)bh * TT * HD;
    float* Kg = g_k + (size_t)bh * TT * HD;

#pragma unroll
    for (int i = 0; i < 8; i++) {
        int p = tid + i * 256;
        int t = t0 + (p >> 5), j = p & 31;
        float cs = cosp[t * 32 + j], sn = sinp[t * 32 + j];
        float q1 = Qg[t * HD + j], q2 = Qg[t * HD + j + 32];
        Qg[t * HD + j]      = __uint_as_float(cvt_tf32((q1 * cs + q2 * sn) * QSCALE));
        Qg[t * HD + j + 32] = __uint_as_float(cvt_tf32((-q1 * sn + q2 * cs) * QSCALE));
        float k1 = Kg[t * HD + j], k2 = Kg[t * HD + j + 32];
        Kg[t * HD + j]      = __uint_as_float(cvt_tf32(k1 * cs + k2 * sn));
        Kg[t * HD + j + 32] = __uint_as_float(cvt_tf32(-k1 * sn + k2 * cs));
    }
}

// ===========================================================================
// Shared proj-style GEMM body: C = A @ W^T, 128x128 tile, single tf32 mma,
// cp.async double buffered fp32 tiles, rna rounding on fragments.
// ===========================================================================
#define PTILE 18432                  // 128*36*4
#define PSTAGE (2 * PTILE)           // 36864
#define PROJ_SMEM (2 * PSTAGE)       // 73728

__device__ __forceinline__ void proj_body(
    const float* __restrict__ A, const float* __restrict__ W,
    uint32_t sb, int m0, int n0, float c[16][4]) {
    int tid = threadIdx.x, lane = tid & 31, wid = tid >> 5;
    int wm = wid >> 2, wn = wid & 3;

    int arow = wm * 64 + (lane & 7) + ((lane >> 3) & 1) * 8;
    int acol = (lane >> 4) * 4;
    int brow = wn * 32 + (lane & 7) + (lane >> 4) * 8;
    int bcol = ((lane >> 3) & 1) * 4;

    // preload stage 0
#pragma unroll
    for (int i = 0; i < 4; i++) {
        int id = tid + i * 256;
        int row = id >> 3, ch = (id & 7) * 4;
        CP16(sb + (uint32_t)(row * 36 + ch) * 4, A + (size_t)(m0 + row) * DM + ch);
        CP16(sb + PTILE + (uint32_t)(row * 36 + ch) * 4, W + (size_t)(n0 + row) * DM + ch);
    }
    CPCOMMIT();

    for (int kc = 0; kc < 16; kc++) {
        if (kc + 1 < 16) {
            uint32_t st = sb + ((kc + 1) & 1) * PSTAGE;
            int k0 = (kc + 1) * 32;
#pragma unroll
            for (int i = 0; i < 4; i++) {
                int id = tid + i * 256;
                int row = id >> 3, ch = (id & 7) * 4;
                CP16(st + (uint32_t)(row * 36 + ch) * 4,
                     A + (size_t)(m0 + row) * DM + k0 + ch);
                CP16(st + PTILE + (uint32_t)(row * 36 + ch) * 4,
                     W + (size_t)(n0 + row) * DM + k0 + ch);
            }
            CPCOMMIT();
            CPWAIT1();
        } else {
            CPWAIT0();
        }
        __syncthreads();

        uint32_t sA = sb + (kc & 1) * PSTAGE;
        uint32_t sB = sA + PTILE;

#pragma unroll
        for (int ks = 0; ks < 4; ks++) {
            uint32_t a[4][4];
#pragma unroll
            for (int ma = 0; ma < 4; ma++) {
                ldsm4(a[ma], sA + (uint32_t)((arow + ma * 16) * 36 + acol + ks * 8) * 4);
#pragma unroll
                for (int j = 0; j < 4; j++) a[ma][j] = cvt_tf32u(a[ma][j]);
            }
#pragma unroll
            for (int p = 0; p < 2; p++) {
                uint32_t b[4];
                ldsm4(b, sB + (uint32_t)((brow + p * 16) * 36 + bcol + ks * 8) * 4);
#pragma unroll
                for (int j = 0; j < 4; j++) b[j] = cvt_tf32u(b[j]);
#pragma unroll
                for (int ma = 0; ma < 4; ma++) {
                    mma8(c[ma * 4 + 2 * p], a[ma], b[0], b[1]);
                    mma8(c[ma * 4 + 2 * p + 1], a[ma], b[2], b[3]);
                }
            }
        }
        __syncthreads();
    }
}

// Output projection: out = g_y @ Wp^T. grid = (4, 64), 2 CTAs/SM.
__global__ __launch_bounds__(256, 2) void proj_mma_kernel(
    const float* __restrict__ Wp, float* __restrict__ out) {
    extern __shared__ uint32_t smp[];
    uint32_t sb = smem_u32(smp);
    int m0 = blockIdx.y * 128, n0 = blockIdx.x * 128;
    int tid = threadIdx.x, lane = tid & 31, wid = tid >> 5;
    int wm = wid >> 2, wn = wid & 3;

    float c[16][4] = {};
    proj_body(g_y, Wp, sb, m0, n0, c);

#pragma unroll
    for (int ma = 0; ma < 4; ma++) {
#pragma unroll
        for (int na = 0; na < 4; na++) {
            int n = n0 + wn * 32 + na * 8 + 2 * (lane & 3);
#pragma unroll
            for (int half = 0; half < 2; half++) {
                int m = m0 + wm * 64 + ma * 16 + (lane >> 2) + half * 8;
                float2 v = make_float2(c[ma * 4 + na][half * 2],
                                       c[ma * 4 + na][half * 2 + 1]);
                *(float2*)&out[(size_t)m * DM + n] = v;
            }
        }
    }
}

// V projection: v = x @ Wv^T, written transposed+tf32-rounded to g_vt.
// grid = (4, 64), 2 CTAs/SM.
__global__ __launch_bounds__(256, 2) void vproj_mma_kernel(
    const float* __restrict__ x, const float* __restrict__ Wv) {
    extern __shared__ uint32_t smp[];
    uint32_t sb = smem_u32(smp);
    int m0 = blockIdx.y * 128, n0 = blockIdx.x * 128;
    int tid = threadIdx.x, lane = tid & 31, wid = tid >> 5;
    int wm = wid >> 2, wn = wid & 3;

    float c[16][4] = {};
    proj_body(x, Wv, sb, m0, n0, c);

    // transpose via smem (stride 132), write g_vt coalesced
    float* smf = (float*)smp;   // 128*132*4 = 67584 <= 73728
#pragma unroll
    for (int ma = 0; ma < 4; ma++) {
#pragma unroll
        for (int na = 0; na < 4; na++) {
            int nl = wn * 32 + na * 8 + 2 * (lane & 3);
#pragma unroll
            for (int half = 0; half < 2; half++) {
                int ml = wm * 64 + ma * 16 + (lane >> 2) + half * 8;
                smf[(nl + 0) * 132 + ml] =
                    __uint_as_float(cvt_tf32(c[ma * 4 + na][half * 2]));
                smf[(nl + 1) * 132 + ml] =
                    __uint_as_float(cvt_tf32(c[ma * 4 + na][half * 2 + 1]));
            }
        }
    }
    __syncthreads();
    int b = m0 >> 12;
    int t0 = m0 & (TT - 1);
#pragma unroll
    for (int i = 0; i < 16; i++) {
        int idx = tid + i * 256;
        int nl = idx >> 5, c4 = (idx & 31) * 4;
        float4 v = *(float4*)&smf[nl * 132 + c4];
        int n = n0 + nl;
        int h = n >> 6, d = n & 63;
        *(float4*)&g_vt[((size_t)(b * HH + h) * HD + d) * TT + t0 + c4] = v;
    }
}

// ===========================================================================
// Flash attention (R12 body), tf32 mma, q-tile 256, 512 threads. PAIRED
// q-tiles (qt = 15-bx then bx) -> uniform 17 k-tiles/CTA, grid (8,16).
// SMEM: Q[256][68] + 2x K[128][68] + 2x Vt[64][132] = 202KB
// ===========================================================================
#define MQ 256
#define KBUF   34816             // 128*68*4
#define VTBUF  33792             // 64*132*4
#define SK_OFF 69632             // after Q 256*68*4
#define SVT_OFF 139264
#define ATTN_SMEM 206848

__global__ __launch_bounds__(512) void attn_mma_kernel() {
    extern __shared__ float sma[];
    uint32_t sb = smem_u32(sma);
    uint32_t sQ = sb;

    int tid = threadIdx.x, lane = tid & 31, wid = tid >> 5;
    int bx = blockIdx.x;        // 0..7
    int bh = blockIdx.y;

    const float* Qg  = g_q  + (size_t)bh * TT * HD;
    const float* Kg  = g_k  + (size_t)bh * TT * HD;
    const float* Vtg = g_vt + (size_t)bh * HD * TT;

    int qrow = wid * 16 + (lane & 7) + ((lane >> 3) & 1) * 8;
    uint32_t qbase = sQ + (uint32_t)(qrow * 68 + (lane >> 4) * 4) * 4;
    uint32_t klane = (uint32_t)(((lane & 7) + (lane >> 4) * 8) * 68 + ((lane >> 3) & 1) * 4) * 4;
    uint32_t vlane = (uint32_t)(((lane & 7) + (lane >> 4) * 8) * 132 + ((lane >> 3) & 1) * 4) * 4;
    int myr0 = wid * 16 + (lane >> 2);

#pragma unroll 1
    for (int pass = 0; pass < 2; pass++) {
        int qt = pass ? bx : (15 - bx);   // big tile first
        int q0 = qt * MQ;

        // Q tile: 256x64 -> 4096 16B chunks, 8/thread
#pragma unroll
        for (int i = 0; i < 8; i++) {
            int id = tid + i * 512;
            int r = id >> 4, c4 = (id & 15) * 4;
            CP16(sQ + (uint32_t)(r * 68 + c4) * 4, Qg + (size_t)(q0 + r) * HD + c4);
        }
        // K/Vt tile 0 -> buf 0
#pragma unroll
        for (int i = 0; i < 4; i++) {
            int id = tid + i * 512;
            int r = id >> 4, c4 = (id & 15) * 4;
            CP16(sb + SK_OFF + (uint32_t)(r * 68 + c4) * 4, Kg + (size_t)r * HD + c4);
            int d = id >> 5, c8 = (id & 31) * 4;
            CP16(sb + SVT_OFF + (uint32_t)(d * 132 + c8) * 4, Vtg + (size_t)d * TT + c8);
        }
        CPCOMMIT();

        float o[8][4] = {};
        float lsum0 = 0.f, lsum1 = 0.f;
        int wrow_lo = q0 + wid * 16;
        int wrow_hi = wrow_lo + 15;
        int nk = (q0 + MQ) >> 7;

        for (int kt = 0; kt < nk; kt++) {
            if (kt + 1 < nk) {
                int buf = (kt + 1) & 1;
                const float* Ks = Kg + (size_t)(kt + 1) * 128 * HD;
                const float* Vs = Vtg + (size_t)(kt + 1) * 128;
#pragma unroll
                for (int i = 0; i < 4; i++) {
                    int id = tid + i * 512;
                    int r = id >> 4, c4 = (id & 15) * 4;
                    CP16(sb + SK_OFF + buf * KBUF + (uint32_t)(r * 68 + c4) * 4,
                         Ks + (size_t)r * HD + c4);
                    int d = id >> 5, c8 = (id & 31) * 4;
                    CP16(sb + SVT_OFF + buf * VTBUF + (uint32_t)(d * 132 + c8) * 4,
                         Vs + (size_t)d * TT + c8);
                }
                CPCOMMIT();
                CPWAIT1();
            } else {
                CPWAIT0();
            }
            __syncthreads();

            uint32_t kb = sb + SK_OFF + (kt & 1) * KBUF + klane;
            uint32_t vb = sb + SVT_OFF + (kt & 1) * VTBUF + vlane;

#pragma unroll
            for (int h = 0; h < 2; h++) {
                int col0 = kt * 128 + h * 64;
                if (col0 > wrow_hi) continue;

                // S = Q K^T : 16x64, K=64 (8 ksteps)
                float c[32];
#pragma unroll
                for (int i = 0; i < 32; i++) c[i] = 0.f;
#pragma unroll
                for (int ks = 0; ks < 8; ks++) {
                    uint32_t a[4];
                    ldsm4(a, qbase + ks * 32);
#pragma unroll
                    for (int p = 0; p < 4; p++) {
                        uint32_t b[4];
                        ldsm4(b, kb + (uint32_t)((h * 64 + p * 16) * 68) * 4 + ks * 32);
                        mma8(&c[(2 * p) * 4], a, b[0], b[1]);
                        mma8(&c[(2 * p + 1) * 4], a, b[2], b[3]);
                    }
                }

                // softmax via exp2 + causal mask; P rounded rna to tf32
                bool needmask = (col0 + 63 > wrow_lo);
#pragma unroll
                for (int na = 0; na < 8; na++) {
#pragma unroll
                    for (int q = 0; q < 4; q++) {
                        float p = exp2f(c[na * 4 + q]);
                        if (needmask) {
                            int colg = col0 + na * 8 + 2 * (lane & 3) + (q & 1);
                            int rowg = q0 + myr0 + (q >> 1) * 8;
                            if (colg > rowg) p = 0.f;
                        }
                        if (q < 2) lsum0 += p; else lsum1 += p;
                        c[na * 4 + q] = __uint_as_float(cvt_tf32(p));
                    }
                }

                // O += P V
                int src  = (lane & 28) | ((lane & 3) >> 1);
                int src2 = src + 2;
                bool odd = lane & 1;
#pragma unroll
                for (int kk = 0; kk < 8; kk++) {
                    float f0 = __shfl_sync(0xffffffffu, c[kk * 4 + 0], src);
                    float f1 = __shfl_sync(0xffffffffu, c[kk * 4 + 1], src);
                    float f2 = __shfl_sync(0xffffffffu, c[kk * 4 + 2], src);
                    float f3 = __shfl_sync(0xffffffffu, c[kk * 4 + 3], src);
                    float g0 = __shfl_sync(0xffffffffu, c[kk * 4 + 0], src2);
                    float g1 = __shfl_sync(0xffffffffu, c[kk * 4 + 1], src2);
                    float g2 = __shfl_sync(0xffffffffu, c[kk * 4 + 2], src2);
                    float g3 = __shfl_sync(0xffffffffu, c[kk * 4 + 3], src2);
                    uint32_t a[4];
                    a[0] = __float_as_uint(odd ? f1 : f0);
                    a[1] = __float_as_uint(odd ? f3 : f2);
                    a[2] = __float_as_uint(odd ? g1 : g0);
                    a[3] = __float_as_uint(odd ? g3 : g2);
#pragma unroll
                    for (int pb = 0; pb < 4; pb++) {
                        uint32_t b[4];
                        ldsm4(b, vb + (uint32_t)(pb * 16 * 132) * 4 + (h * 8 + kk) * 32);
                        mma8(o[pb * 2], a, b[0], b[1]);
                        mma8(o[pb * 2 + 1], a, b[2], b[3]);
                    }
                }
            }
            __syncthreads();
        }

        lsum0 += __shfl_xor_sync(0xffffffffu, lsum0, 1);
        lsum0 += __shfl_xor_sync(0xffffffffu, lsum0, 2);
        lsum1 += __shfl_xor_sync(0xffffffffu, lsum1, 1);
        lsum1 += __shfl_xor_sync(0xffffffffu, lsum1, 2);
        float inv0 = 1.f / lsum0, inv1 = 1.f / lsum1;

        int b = bh >> 3, h = bh & 7;
        int t0 = q0 + myr0, t1 = t0 + 8;
        float* dst0 = g_y + ((size_t)(b * TT + t0)) * DM + h * 64;
        float* dst1 = g_y + ((size_t)(b * TT + t1)) * DM + h * 64;
#pragma unroll
        for (int nd = 0; nd < 8; nd++) {
            int col = nd * 8 + 2 * (lane & 3);
            *(float2*)(dst0 + col) = make_float2(o[nd][0] * inv0, o[nd][1] * inv0);
            *(float2*)(dst1 + col) = make_float2(o[nd][2] * inv1, o[nd][3] * inv1);
        }
        __syncthreads();   // all warps done with smem before next pass reloads
    }
}

// ===========================================================================
extern "C" void kernel_launch(void* const* d_in, const int* in_sizes, int n_in,
                              void* d_out, int out_size) {
    const float* x    = (const float*)d_in[0];
    const float* cosp = (const float*)d_in[1];
    const float* sinp = (const float*)d_in[2];
    const float* Wq   = (const float*)d_in[3];
    const float* Wk   = (const float*)d_in[4];
    const float* Wv   = (const float*)d_in[5];
    const float* Wp   = (const float*)d_in[6];
    float* out = (float*)d_out;

    cudaFuncSetAttribute(qkv_mma_kernel,
                         cudaFuncAttributeMaxDynamicSharedMemorySize, QKV_SMEM);
    cudaFuncSetAttribute(attn_mma_kernel,
                         cudaFuncAttributeMaxDynamicSharedMemorySize, ATTN_SMEM);
    cudaFuncSetAttribute(proj_mma_kernel,
                         cudaFuncAttributeMaxDynamicSharedMemorySize, PROJ_SMEM);
    cudaFuncSetAttribute(vproj_mma_kernel,
                         cudaFuncAttributeMaxDynamicSharedMemorySize, PROJ_SMEM);

    dim3 gq(DM / 128, BT / 128, 2);
    qkv_mma_kernel<<<gq, 256, QKV_SMEM>>>(x, Wq, Wk);

    dim3 gv(DM / 128, BT / 128);
    vproj_mma_kernel<<<gv, 256, PROJ_SMEM>>>(x, Wv);

    dim3 gp0(TT / 64, BB * HH);
    prep_kernel<<<gp0, 256>>>(cosp, sinp);

    dim3 ga(TT / (2 * MQ), BB * HH);
    attn_mma_kernel<<<ga, 512, ATTN_SMEM>>>();

    dim3 gp(DM / 128, BT / 128);
    proj_mma_kernel<<<gp, 256, PROJ_SMEM>>>(Wp, out);
}

// round 16
// speedup vs baseline: 1.0870x; 1.0271x over previous
#include <cuda_runtime.h>
#include <cstdint>

#define BB 2
#define TT 4096
#define HH 8
#define HD 64
#define DM 512
#define BT (BB*TT)

// Scratch (__device__ globals; no allocs allowed)
__device__ float g_q[BB*HH*TT*HD];
__device__ float g_k[BB*HH*TT*HD];
__device__ float g_vt[BB*HH*HD*TT];   // transposed, tf32-rounded V
__device__ float g_y[(size_t)BT*DM];

// ===========================================================================
// helpers
// ===========================================================================
__device__ __forceinline__ uint32_t smem_u32(const void* p) {
    uint32_t a;
    asm("{ .reg .u64 t; cvta.to.shared.u64 t, %1; cvt.u32.u64 %0, t; }"
        : "=r"(a) : "l"(p));
    return a;
}
__device__ __forceinline__ uint32_t cvt_tf32(float x) {
    uint32_t u;
    asm("cvt.rna.tf32.f32 %0, %1;" : "=r"(u) : "f"(x));
    return u;
}
__device__ __forceinline__ uint32_t cvt_tf32u(uint32_t x) {
    uint32_t u;
    asm("cvt.rna.tf32.f32 %0, %1;" : "=r"(u) : "r"(x));
    return u;
}
__device__ __forceinline__ void ldsm4(uint32_t a[4], uint32_t addr) {
    asm volatile("ldmatrix.sync.aligned.m8n8.x4.shared.b16 {%0,%1,%2,%3}, [%4];"
        : "=r"(a[0]), "=r"(a[1]), "=r"(a[2]), "=r"(a[3]) : "r"(addr));
}
__device__ __forceinline__ void mma8(float c[4], const uint32_t a[4],
                                     uint32_t b0, uint32_t b1) {
    asm volatile(
        "mma.sync.aligned.m16n8k8.row.col.f32.tf32.tf32.f32 "
        "{%0,%1,%2,%3}, {%4,%5,%6,%7}, {%8,%9}, {%0,%1,%2,%3};"
        : "+f"(c[0]), "+f"(c[1]), "+f"(c[2]), "+f"(c[3])
        : "r"(a[0]), "r"(a[1]), "r"(a[2]), "r"(a[3]), "r"(b0), "r"(b1));
}
__device__ __forceinline__ void mma16(float c[4], const uint32_t a[4],
                                      uint32_t b0, uint32_t b1) {
    asm volatile(
        "mma.sync.aligned.m16n8k16.row.col.f32.bf16.bf16.f32 "
        "{%0,%1,%2,%3}, {%4,%5,%6,%7}, {%8,%9}, {%0,%1,%2,%3};"
        : "+f"(c[0]), "+f"(c[1]), "+f"(c[2]), "+f"(c[3])
        : "r"(a[0]), "r"(a[1]), "r"(a[2]), "r"(a[3]), "r"(b0), "r"(b1));
}
__device__ __forceinline__ void split_bf16(float v, uint16_t& h, uint16_t& l) {
    asm("cvt.rn.bf16.f32 %0, %1;" : "=h"(h) : "f"(v));
    float hf = __uint_as_float((uint32_t)h << 16);
    asm("cvt.rn.bf16.f32 %0, %1;" : "=h"(l) : "f"(v - hf));
}

#define CP16(dst, src) \
    asm volatile("cp.async.cg.shared.global [%0], [%1], 16;" \
                 :: "r"(dst), "l"(src) : "memory")
#define CPCOMMIT() asm volatile("cp.async.commit_group;" ::: "memory")
#define CPWAIT1()  asm volatile("cp.async.wait_group 1;" ::: "memory")
#define CPWAIT0()  asm volatile("cp.async.wait_group 0;" ::: "memory")

// ===========================================================================
// Q/K projection: bf16 split hi/lo inline, 3 mma products.
// C = x @ W^T. CTA 128x128, 8 warps (2x4), warp tile 64x32, kchunk 32.
// grid = (4, 64, 2). smem: Ah/Al/Bh/Bl bf16 tiles [128][40] = 40KB.
// ===========================================================================
#define QKV_SMEM (4 * 128 * 40 * 2)

__global__ __launch_bounds__(256, 2) void qkv_mma_kernel(
    const float* __restrict__ x,
    const float* __restrict__ Wq, const float* __restrict__ Wk) {
    extern __shared__ uint32_t smq[];
    uint32_t* Ah32 = smq;
    uint32_t* Al32 = smq + 2560;
    uint32_t* Bh32 = smq + 5120;
    uint32_t* Bl32 = smq + 7680;
    uint32_t sb = smem_u32(smq);
    uint32_t sAh = sb, sAl = sb + 10240, sBh = sb + 20480, sBl = sb + 30720;

    const float* W = (blockIdx.z == 0) ? Wq : Wk;
    float* outp    = (blockIdx.z == 0) ? g_q : g_k;

    int m0 = blockIdx.y * 128, n0 = blockIdx.x * 128;
    int tid = threadIdx.x, lane = tid & 31, wid = tid >> 5;
    int wm = wid >> 2, wn = wid & 3;

    float c[16][4] = {};

    int lrow = (lane & 7) + ((lane >> 3) & 1) * 8;
    int lk   = (lane >> 4) * 8;

    for (int kc = 0; kc < 16; kc++) {
        int k0 = kc * 32;
        __syncthreads();
#pragma unroll
        for (int i = 0; i < 4; i++) {
            int id = tid + i * 256;
            int row = id >> 3, kq = (id & 7) * 4;
            int idx = row * 20 + (kq >> 1);
            float4 v = *(const float4*)(x + (size_t)(m0 + row) * DM + k0 + kq);
            uint16_t hx, lx, hy, ly, hz, lz, hw, lw;
            split_bf16(v.x, hx, lx); split_bf16(v.y, hy, ly);
            split_bf16(v.z, hz, lz); split_bf16(v.w, hw, lw);
            Ah32[idx]     = (uint32_t)hx | ((uint32_t)hy << 16);
            Ah32[idx + 1] = (uint32_t)hz | ((uint32_t)hw << 16);
            Al32[idx]     = (uint32_t)lx | ((uint32_t)ly << 16);
            Al32[idx + 1] = (uint32_t)lz | ((uint32_t)lw << 16);
            float4 w = *(const float4*)(W + (size_t)(n0 + row) * DM + k0 + kq);
            split_bf16(w.x, hx, lx); split_bf16(w.y, hy, ly);
            split_bf16(w.z, hz, lz); split_bf16(w.w, hw, lw);
            Bh32[idx]     = (uint32_t)hx | ((uint32_t)hy << 16);
            Bh32[idx + 1] = (uint32_t)hz | ((uint32_t)hw << 16);
            Bl32[idx]     = (uint32_t)lx | ((uint32_t)ly << 16);
            Bl32[idx + 1] = (uint32_t)lz | ((uint32_t)lw << 16);
        }
        __syncthreads();

#pragma unroll
        for (int ks = 0; ks < 2; ks++) {
            uint32_t boff0 = (uint32_t)((wn * 32 + lrow) * 40 + lk + ks * 16) * 2;
            uint32_t boff1 = (uint32_t)((wn * 32 + 16 + lrow) * 40 + lk + ks * 16) * 2;
            uint32_t bh0[4], bl0[4], bh1[4], bl1[4];
            ldsm4(bh0, sBh + boff0);
            ldsm4(bl0, sBl + boff0);
            ldsm4(bh1, sBh + boff1);
            ldsm4(bl1, sBl + boff1);
#pragma unroll
            for (int ma = 0; ma < 4; ma++) {
                uint32_t aoff = (uint32_t)((wm * 64 + ma * 16 + lrow) * 40 + lk + ks * 16) * 2;
                uint32_t ah[4], al[4];
                ldsm4(ah, sAh + aoff);
                ldsm4(al, sAl + aoff);
                mma16(c[ma * 4 + 0], ah, bh0[0], bh0[2]);
                mma16(c[ma * 4 + 0], ah, bl0[0], bl0[2]);
                mma16(c[ma * 4 + 0], al, bh0[0], bh0[2]);
                mma16(c[ma * 4 + 1], ah, bh0[1], bh0[3]);
                mma16(c[ma * 4 + 1], ah, bl0[1], bl0[3]);
                mma16(c[ma * 4 + 1], al, bh0[1], bh0[3]);
                mma16(c[ma * 4 + 2], ah, bh1[0], bh1[2]);
                mma16(c[ma * 4 + 2], ah, bl1[0], bl1[2]);
                mma16(c[ma * 4 + 2], al, bh1[0], bh1[2]);
                mma16(c[ma * 4 + 3], ah, bh1[1], bh1[3]);
                mma16(c[ma * 4 + 3], ah, bl1[1], bl1[3]);
                mma16(c[ma * 4 + 3], al, bh1[1], bh1[3]);
            }
        }
    }

    // epilogue -> (B,H,T,hd)
#pragma unroll
    for (int ma = 0; ma < 4; ma++) {
#pragma unroll
        for (int na = 0; na < 4; na++) {
            int n = n0 + wn * 32 + na * 8 + 2 * (lane & 3);
            int h = n >> 6, d = n & 63;
#pragma unroll
            for (int half = 0; half < 2; half++) {
                int m = m0 + wm * 64 + ma * 16 + (lane >> 2) + half * 8;
                int b = m >> 12, t = m & (TT - 1);
                float2 v = make_float2(c[ma * 4 + na][half * 2],
                                       c[ma * 4 + na][half * 2 + 1]);
                *(float2*)&outp[(((size_t)(b * HH + h)) * TT + t) * HD + d] = v;
            }
        }
    }
}

// ===========================================================================
// Prep: RoPE + (scale*log2e) + tf32 for q, RoPE+tf32 for k (in place).
// grid = (TT/64, BB*HH).
// ===========================================================================
#define QSCALE 0.1803368801111204f   /* 0.125 * log2(e) */

__global__ __launch_bounds__(256) void prep_kernel(
    const float* __restrict__ cosp, const float* __restrict__ sinp) {
    int bh = blockIdx.y;
    int t0 = blockIdx.x * 64;
    int tid = threadIdx.x;
    float* Qg = g_q + (size_t)bh * TT * HD;
    float* Kg = g_k + (size_t)bh * TT * HD;

#pragma unroll
    for (int i = 0; i < 8; i++) {
        int p = tid + i * 256;
        int t = t0 + (p >> 5), j = p & 31;
        float cs = cosp[t * 32 + j], sn = sinp[t * 32 + j];
        float q1 = Qg[t * HD + j], q2 = Qg[t * HD + j + 32];
        Qg[t * HD + j]      = __uint_as_float(cvt_tf32((q1 * cs + q2 * sn) * QSCALE));
        Qg[t * HD + j + 32] = __uint_as_float(cvt_tf32((-q1 * sn + q2 * cs) * QSCALE));
        float k1 = Kg[t * HD + j], k2 = Kg[t * HD + j + 32];
        Kg[t * HD + j]      = __uint_as_float(cvt_tf32(k1 * cs + k2 * sn));
        Kg[t * HD + j + 32] = __uint_as_float(cvt_tf32(-k1 * sn + k2 * cs));
    }
}

// ===========================================================================
// Shared proj-style GEMM body: C = A @ W^T, 128x128 tile, single tf32 mma,
// cp.async double buffered fp32 tiles, rna rounding on fragments.
// ===========================================================================
#define PTILE 18432                  // 128*36*4
#define PSTAGE (2 * PTILE)           // 36864
#define PROJ_SMEM (2 * PSTAGE)       // 73728

__device__ __forceinline__ void proj_body(
    const float* __restrict__ A, const float* __restrict__ W,
    uint32_t sb, int m0, int n0, float c[16][4]) {
    int tid = threadIdx.x, lane = tid & 31, wid = tid >> 5;
    int wm = wid >> 2, wn = wid & 3;

    int arow = wm * 64 + (lane & 7) + ((lane >> 3) & 1) * 8;
    int acol = (lane >> 4) * 4;
    int brow = wn * 32 + (lane & 7) + (lane >> 4) * 8;
    int bcol = ((lane >> 3) & 1) * 4;

    // preload stage 0
#pragma unroll
    for (int i = 0; i < 4; i++) {
        int id = tid + i * 256;
        int row = id >> 3, ch = (id & 7) * 4;
        CP16(sb + (uint32_t)(row * 36 + ch) * 4, A + (size_t)(m0 + row) * DM + ch);
        CP16(sb + PTILE + (uint32_t)(row * 36 + ch) * 4, W + (size_t)(n0 + row) * DM + ch);
    }
    CPCOMMIT();

    for (int kc = 0; kc < 16; kc++) {
        if (kc + 1 < 16) {
            uint32_t st = sb + ((kc + 1) & 1) * PSTAGE;
            int k0 = (kc + 1) * 32;
#pragma unroll
            for (int i = 0; i < 4; i++) {
                int id = tid + i * 256;
                int row = id >> 3, ch = (id & 7) * 4;
                CP16(st + (uint32_t)(row * 36 + ch) * 4,
                     A + (size_t)(m0 + row) * DM + k0 + ch);
                CP16(st + PTILE + (uint32_t)(row * 36 + ch) * 4,
                     W + (size_t)(n0 + row) * DM + k0 + ch);
            }
            CPCOMMIT();
            CPWAIT1();
        } else {
            CPWAIT0();
        }
        __syncthreads();

        uint32_t sA = sb + (kc & 1) * PSTAGE;
        uint32_t sB = sA + PTILE;

#pragma unroll
        for (int ks = 0; ks < 4; ks++) {
            uint32_t a[4][4];
#pragma unroll
            for (int ma = 0; ma < 4; ma++) {
                ldsm4(a[ma], sA + (uint32_t)((arow + ma * 16) * 36 + acol + ks * 8) * 4);
#pragma unroll
                for (int j = 0; j < 4; j++) a[ma][j] = cvt_tf32u(a[ma][j]);
            }
#pragma unroll
            for (int p = 0; p < 2; p++) {
                uint32_t b[4];
                ldsm4(b, sB + (uint32_t)((brow + p * 16) * 36 + bcol + ks * 8) * 4);
#pragma unroll
                for (int j = 0; j < 4; j++) b[j] = cvt_tf32u(b[j]);
#pragma unroll
                for (int ma = 0; ma < 4; ma++) {
                    mma8(c[ma * 4 + 2 * p], a[ma], b[0], b[1]);
                    mma8(c[ma * 4 + 2 * p + 1], a[ma], b[2], b[3]);
                }
            }
        }
        __syncthreads();
    }
}

// Output projection: out = g_y @ Wp^T. grid = (4, 64), 2 CTAs/SM.
__global__ __launch_bounds__(256, 2) void proj_mma_kernel(
    const float* __restrict__ Wp, float* __restrict__ out) {
    extern __shared__ uint32_t smp[];
    uint32_t sb = smem_u32(smp);
    int m0 = blockIdx.y * 128, n0 = blockIdx.x * 128;
    int tid = threadIdx.x, lane = tid & 31, wid = tid >> 5;
    int wm = wid >> 2, wn = wid & 3;

    float c[16][4] = {};
    proj_body(g_y, Wp, sb, m0, n0, c);

#pragma unroll
    for (int ma = 0; ma < 4; ma++) {
#pragma unroll
        for (int na = 0; na < 4; na++) {
            int n = n0 + wn * 32 + na * 8 + 2 * (lane & 3);
#pragma unroll
            for (int half = 0; half < 2; half++) {
                int m = m0 + wm * 64 + ma * 16 + (lane >> 2) + half * 8;
                float2 v = make_float2(c[ma * 4 + na][half * 2],
                                       c[ma * 4 + na][half * 2 + 1]);
                *(float2*)&out[(size_t)m * DM + n] = v;
            }
        }
    }
}

// V projection: v = x @ Wv^T, written transposed+tf32-rounded to g_vt.
// grid = (4, 64), 2 CTAs/SM.
__global__ __launch_bounds__(256, 2) void vproj_mma_kernel(
    const float* __restrict__ x, const float* __restrict__ Wv) {
    extern __shared__ uint32_t smp[];
    uint32_t sb = smem_u32(smp);
    int m0 = blockIdx.y * 128, n0 = blockIdx.x * 128;
    int tid = threadIdx.x, lane = tid & 31, wid = tid >> 5;
    int wm = wid >> 2, wn = wid & 3;

    float c[16][4] = {};
    proj_body(x, Wv, sb, m0, n0, c);

    // transpose via smem (stride 132), write g_vt coalesced
    float* smf = (float*)smp;   // 128*132*4 = 67584 <= 73728
#pragma unroll
    for (int ma = 0; ma < 4; ma++) {
#pragma unroll
        for (int na = 0; na < 4; na++) {
            int nl = wn * 32 + na * 8 + 2 * (lane & 3);
#pragma unroll
            for (int half = 0; half < 2; half++) {
                int ml = wm * 64 + ma * 16 + (lane >> 2) + half * 8;
                smf[(nl + 0) * 132 + ml] =
                    __uint_as_float(cvt_tf32(c[ma * 4 + na][half * 2]));
                smf[(nl + 1) * 132 + ml] =
                    __uint_as_float(cvt_tf32(c[ma * 4 + na][half * 2 + 1]));
            }
        }
    }
    __syncthreads();
    int b = m0 >> 12;
    int t0 = m0 & (TT - 1);
#pragma unroll
    for (int i = 0; i < 16; i++) {
        int idx = tid + i * 256;
        int nl = idx >> 5, c4 = (idx & 31) * 4;
        float4 v = *(float4*)&smf[nl * 132 + c4];
        int n = n0 + nl;
        int h = n >> 6, d = n & 63;
        *(float4*)&g_vt[((size_t)(b * HH + h) * HD + d) * TT + t0 + c4] = v;
    }
}

// ===========================================================================
// Flash attention, tf32 mma, q-tile 256, 256 threads (8 warps x 32 q-rows).
// K/V fragments amortize over 2 m-tiles -> ~55% of prior smem traffic.
// PAIRED q-tiles (qt = 15-bx then bx) -> uniform work, grid (8,16).
// SMEM: Q[256][68] + 2x K[128][68] + 2x Vt[64][132] = 202KB
// ===========================================================================
#define MQ 256
#define KBUF   34816             // 128*68*4
#define VTBUF  33792             // 64*132*4
#define SK_OFF 69632             // after Q 256*68*4
#define SVT_OFF 139264
#define ATTN_SMEM 206848

__global__ __launch_bounds__(256) void attn_mma_kernel() {
    extern __shared__ float sma[];
    uint32_t sb = smem_u32(sma);
    uint32_t sQ = sb;

    int tid = threadIdx.x, lane = tid & 31, wid = tid >> 5;  // wid 0..7
    int bx = blockIdx.x;        // 0..7
    int bh = blockIdx.y;

    const float* Qg  = g_q  + (size_t)bh * TT * HD;
    const float* Kg  = g_k  + (size_t)bh * TT * HD;
    const float* Vtg = g_vt + (size_t)bh * HD * TT;

    // warp q-rows: wid*32 .. wid*32+31 (two 16-row m-tiles)
    int qrow0 = wid * 32 + (lane & 7) + ((lane >> 3) & 1) * 8;   // + ma*16
    uint32_t qbase = sQ + (uint32_t)(qrow0 * 68 + (lane >> 4) * 4) * 4;
    uint32_t klane = (uint32_t)(((lane & 7) + (lane >> 4) * 8) * 68 + ((lane >> 3) & 1) * 4) * 4;
    uint32_t vlane = (uint32_t)(((lane & 7) + (lane >> 4) * 8) * 132 + ((lane >> 3) & 1) * 4) * 4;
    int myr0 = wid * 32 + (lane >> 2);   // + ma*16 + (q>>1)*8

#pragma unroll 1
    for (int pass = 0; pass < 2; pass++) {
        int qt = pass ? bx : (15 - bx);   // big tile first
        int q0 = qt * MQ;

        // Q tile: 256x64 -> 4096 16B chunks, 16/thread
#pragma unroll
        for (int i = 0; i < 16; i++) {
            int id = tid + i * 256;
            int r = id >> 4, c4 = (id & 15) * 4;
            CP16(sQ + (uint32_t)(r * 68 + c4) * 4, Qg + (size_t)(q0 + r) * HD + c4);
        }
        // K/Vt tile 0 -> buf 0 (each 2048 chunks, 8/thread)
#pragma unroll
        for (int i = 0; i < 8; i++) {
            int id = tid + i * 256;
            int r = id >> 4, c4 = (id & 15) * 4;
            CP16(sb + SK_OFF + (uint32_t)(r * 68 + c4) * 4, Kg + (size_t)r * HD + c4);
            int d = id >> 5, c8 = (id & 31) * 4;
            CP16(sb + SVT_OFF + (uint32_t)(d * 132 + c8) * 4, Vtg + (size_t)d * TT + c8);
        }
        CPCOMMIT();

        float o[2][8][4] = {};
        float ls[2][2] = {};
        int wrow_lo = q0 + wid * 32;
        int wrow_hi = wrow_lo + 31;
        int nk = (q0 + MQ) >> 7;

        for (int kt = 0; kt < nk; kt++) {
            if (kt + 1 < nk) {
                int buf = (kt + 1) & 1;
                const float* Ks = Kg + (size_t)(kt + 1) * 128 * HD;
                const float* Vs = Vtg + (size_t)(kt + 1) * 128;
#pragma unroll
                for (int i = 0; i < 8; i++) {
                    int id = tid + i * 256;
                    int r = id >> 4, c4 = (id & 15) * 4;
                    CP16(sb + SK_OFF + buf * KBUF + (uint32_t)(r * 68 + c4) * 4,
                         Ks + (size_t)r * HD + c4);
                    int d = id >> 5, c8 = (id & 31) * 4;
                    CP16(sb + SVT_OFF + buf * VTBUF + (uint32_t)(d * 132 + c8) * 4,
                         Vs + (size_t)d * TT + c8);
                }
                CPCOMMIT();
                CPWAIT1();
            } else {
                CPWAIT0();
            }
            __syncthreads();

            uint32_t kb = sb + SK_OFF + (kt & 1) * KBUF + klane;
            uint32_t vb = sb + SVT_OFF + (kt & 1) * VTBUF + vlane;

#pragma unroll
            for (int h = 0; h < 2; h++) {
                int col0 = kt * 128 + h * 64;
                if (col0 > wrow_hi) continue;

                // S = Q K^T : 32x64 per warp (2 m-tiles), K=64 (8 ksteps)
                float c[2][32];
#pragma unroll
                for (int ma = 0; ma < 2; ma++)
#pragma unroll
                    for (int i = 0; i < 32; i++) c[ma][i] = 0.f;
#pragma unroll
                for (int ks = 0; ks < 8; ks++) {
                    uint32_t aq[2][4];
                    ldsm4(aq[0], qbase + ks * 32);
                    ldsm4(aq[1], qbase + (uint32_t)(16 * 68 * 4) + ks * 32);
#pragma unroll
                    for (int p = 0; p < 4; p++) {
                        uint32_t b[4];
                        ldsm4(b, kb + (uint32_t)((h * 64 + p * 16) * 68) * 4 + ks * 32);
#pragma unroll
                        for (int ma = 0; ma < 2; ma++) {
                            mma8(&c[ma][(2 * p) * 4], aq[ma], b[0], b[1]);
                            mma8(&c[ma][(2 * p + 1) * 4], aq[ma], b[2], b[3]);
                        }
                    }
                }

                // softmax via exp2 + causal mask; P rounded rna to tf32
                bool needmask = (col0 + 63 > wrow_lo);
#pragma unroll
                for (int ma = 0; ma < 2; ma++) {
#pragma unroll
                    for (int na = 0; na < 8; na++) {
#pragma unroll
                        for (int q = 0; q < 4; q++) {
                            float p = exp2f(c[ma][na * 4 + q]);
                            if (needmask) {
                                int colg = col0 + na * 8 + 2 * (lane & 3) + (q & 1);
                                int rowg = q0 + myr0 + ma * 16 + (q >> 1) * 8;
                                if (colg > rowg) p = 0.f;
                            }
                            ls[ma][q >> 1] += p;
                            c[ma][na * 4 + q] = __uint_as_float(cvt_tf32(p));
                        }
                    }
                }

                // O += P V : V b-frags shared across both m-tiles
                int src  = (lane & 28) | ((lane & 3) >> 1);
                int src2 = src + 2;
                bool odd = lane & 1;
#pragma unroll
                for (int kk = 0; kk < 8; kk++) {
                    uint32_t a[2][4];
#pragma unroll
                    for (int ma = 0; ma < 2; ma++) {
                        float f0 = __shfl_sync(0xffffffffu, c[ma][kk * 4 + 0], src);
                        float f1 = __shfl_sync(0xffffffffu, c[ma][kk * 4 + 1], src);
                        float f2 = __shfl_sync(0xffffffffu, c[ma][kk * 4 + 2], src);
                        float f3 = __shfl_sync(0xffffffffu, c[ma][kk * 4 + 3], src);
                        float g0 = __shfl_sync(0xffffffffu, c[ma][kk * 4 + 0], src2);
                        float g1 = __shfl_sync(0xffffffffu, c[ma][kk * 4 + 1], src2);
                        float g2 = __shfl_sync(0xffffffffu, c[ma][kk * 4 + 2], src2);
                        float g3 = __shfl_sync(0xffffffffu, c[ma][kk * 4 + 3], src2);
                        a[ma][0] = __float_as_uint(odd ? f1 : f0);
                        a[ma][1] = __float_as_uint(odd ? f3 : f2);
                        a[ma][2] = __float_as_uint(odd ? g1 : g0);
                        a[ma][3] = __float_as_uint(odd ? g3 : g2);
                    }
#pragma unroll
                    for (int pb = 0; pb < 4; pb++) {
                        uint32_t b[4];
                        ldsm4(b, vb + (uint32_t)(pb * 16 * 132) * 4 + (h * 8 + kk) * 32);
#pragma unroll
                        for (int ma = 0; ma < 2; ma++) {
                            mma8(o[ma][pb * 2], a[ma], b[0], b[1]);
                            mma8(o[ma][pb * 2 + 1], a[ma], b[2], b[3]);
                        }
                    }
                }
            }
            __syncthreads();
        }

        // finalize: quad-reduce sums, write both m-tiles
        int b = bh >> 3, h = bh & 7;
#pragma unroll
        for (int ma = 0; ma < 2; ma++) {
            float l0 = ls[ma][0], l1 = ls[ma][1];
            l0 += __shfl_xor_sync(0xffffffffu, l0, 1);
            l0 += __shfl_xor_sync(0xffffffffu, l0, 2);
            l1 += __shfl_xor_sync(0xffffffffu, l1, 1);
            l1 += __shfl_xor_sync(0xffffffffu, l1, 2);
            float inv0 = 1.f / l0, inv1 = 1.f / l1;
            int t0 = q0 + myr0 + ma * 16, t1 = t0 + 8;
            float* dst0 = g_y + ((size_t)(b * TT + t0)) * DM + h * 64;
            float* dst1 = g_y + ((size_t)(b * TT + t1)) * DM + h * 64;
#pragma unroll
            for (int nd = 0; nd < 8; nd++) {
                int col = nd * 8 + 2 * (lane & 3);
                *(float2*)(dst0 + col) = make_float2(o[ma][nd][0] * inv0,
                                                     o[ma][nd][1] * inv0);
                *(float2*)(dst1 + col) = make_float2(o[ma][nd][2] * inv1,
                                                     o[ma][nd][3] * inv1);
            }
        }
        __syncthreads();   // all warps done with smem before next pass reloads
    }
}

// ===========================================================================
extern "C" void kernel_launch(void* const* d_in, const int* in_sizes, int n_in,
                              void* d_out, int out_size) {
    const float* x    = (const float*)d_in[0];
    const float* cosp = (const float*)d_in[1];
    const float* sinp = (const float*)d_in[2];
    const float* Wq   = (const float*)d_in[3];
    const float* Wk   = (const float*)d_in[4];
    const float* Wv   = (const float*)d_in[5];
    const float* Wp   = (const float*)d_in[6];
    float* out = (float*)d_out;

    cudaFuncSetAttribute(qkv_mma_kernel,
                         cudaFuncAttributeMaxDynamicSharedMemorySize, QKV_SMEM);
    cudaFuncSetAttribute(attn_mma_kernel,
                         cudaFuncAttributeMaxDynamicSharedMemorySize, ATTN_SMEM);
    cudaFuncSetAttribute(proj_mma_kernel,
                         cudaFuncAttributeMaxDynamicSharedMemorySize, PROJ_SMEM);
    cudaFuncSetAttribute(vproj_mma_kernel,
                         cudaFuncAttributeMaxDynamicSharedMemorySize, PROJ_SMEM);

    dim3 gq(DM / 128, BT / 128, 2);
    qkv_mma_kernel<<<gq, 256, QKV_SMEM>>>(x, Wq, Wk);

    dim3 gv(DM / 128, BT / 128);
    vproj_mma_kernel<<<gv, 256, PROJ_SMEM>>>(x, Wv);

    dim3 gp0(TT / 64, BB * HH);
    prep_kernel<<<gp0, 256>>>(cosp, sinp);

    dim3 ga(TT / (2 * MQ), BB * HH);
    attn_mma_kernel<<<ga, 256, ATTN_SMEM>>>();

    dim3 gp(DM / 128, BT / 128);
    proj_mma_kernel<<<gp, 256, PROJ_SMEM>>>(Wp, out);
}